// round 12
// baseline (speedup 1.0000x reference)
#include <cuda_runtime.h>
#include <cuda_fp16.h>

#define NN 100000
#define EE 1600000
#define RR 3
#define FF 128
#define HH 64
#define OO 32
#define BB 50000
#define SCAN_BLKS ((NN + 1023) / 1024)

typedef unsigned long long ull;

// ---------------- scratch ----------------
struct BuildBuf {                 // double-buffered per-relation CSR state
    int deg[NN];
};
__device__ BuildBuf g_bb[2];
__device__ int    g_rowstart2[2][NN];
__device__ ull    g_csr2[2][EE];     // packed (src:int low32, norm:float high32)
__device__ float  g_dinv[NN];        // build-internal (serial on build stream)
__device__ int    g_cursor[NN];
__device__ int    g_bsums[SCAN_BLKS];
__device__ float  g_h1b[2][NN * HH];   // double-buffered conv1 output
__device__ __half g_h1hb[2][NN * HH];
__device__ float  g_x1[NN * HH];
__device__ float  g_h2[NN * OO];
__device__ __half g_h2h[NN * OO];
__device__ float  g_x2[NN * OO];
__device__ float  g_stats[2 * HH];
__device__ float  g_bn[2 * HH];

// ---------------- f32x2 helpers ----------------
__device__ __forceinline__ ull fma2(ull a, ull b, ull c)
{
    ull d;
    asm("fma.rn.f32x2 %0, %1, %2, %3;" : "=l"(d) : "l"(a), "l"(b), "l"(c));
    return d;
}
__device__ __forceinline__ ull pack2(float x, float y)
{
    ull d;
    asm("mov.b64 %0, {%1,%2};" : "=l"(d) : "f"(x), "f"(y));
    return d;
}

// ---------------- tiled GEMM: Y = act(X) @ W + b ; also emits fp16 copy ----
template <int K, int C, bool FUSE>
__global__ __launch_bounds__(256, 2) void gemm_tiled(
    const float* __restrict__ X, const float* __restrict__ Wg,
    const float* __restrict__ bg, const float* __restrict__ bnp,
    float* __restrict__ Y, __half* __restrict__ Yh, int nrows)
{
    constexpr int KB = 32;
    constexpr int CPT = C / 8;
    constexpr int NC2 = CPT / 2;
    __shared__ float sXT[KB][256];
    __shared__ float sW[KB][C];

    int tid = threadIdx.x;
    int rg = tid >> 3;
    int cg = tid & 7;
    int row0 = blockIdx.x * 256;
    int myrow = row0 + tid;
    bool valid = myrow < nrows;

    ull acc[8][NC2];
    {
        const ull* bp = (const ull*)(bg + cg * CPT);
#pragma unroll
        for (int j = 0; j < NC2; j++) {
            ull bv = __ldg(bp + j);
#pragma unroll
            for (int rr = 0; rr < 8; rr++) acc[rr][j] = bv;
        }
    }

    const float4* Xr = (const float4*)(X + (size_t)myrow * K);

    for (int kc = 0; kc < K; kc += KB) {
        {
            const float4* Wt = (const float4*)(Wg + (size_t)kc * C);
#pragma unroll
            for (int i = tid; i < KB * C / 4; i += 256)
                ((float4*)&sW[0][0])[i] = __ldg(Wt + i);
        }
#pragma unroll
        for (int j4 = 0; j4 < KB / 4; j4++) {
            float4 v = valid ? __ldg(Xr + kc / 4 + j4)
                             : make_float4(0.f, 0.f, 0.f, 0.f);
            if (FUSE) {
                float4 a = __ldg((const float4*)bnp + kc / 4 + j4);
                float4 b = __ldg((const float4*)(bnp + K) + kc / 4 + j4);
                v.x = fmaxf(0.f, fmaf(v.x, a.x, b.x));
                v.y = fmaxf(0.f, fmaf(v.y, a.y, b.y));
                v.z = fmaxf(0.f, fmaf(v.z, a.z, b.z));
                v.w = fmaxf(0.f, fmaf(v.w, a.w, b.w));
            }
            sXT[j4 * 4 + 0][tid] = v.x;
            sXT[j4 * 4 + 1][tid] = v.y;
            sXT[j4 * 4 + 2][tid] = v.z;
            sXT[j4 * 4 + 3][tid] = v.w;
        }
        __syncthreads();

#pragma unroll
        for (int k = 0; k < KB; k++) {
            float x[8];
            *(float4*)&x[0] = *(const float4*)&sXT[k][rg * 8];
            *(float4*)&x[4] = *(const float4*)&sXT[k][rg * 8 + 4];
            ull w2[NC2];
#pragma unroll
            for (int j2 = 0; j2 < NC2 / 2; j2++) {
                ulonglong2 wv = *(const ulonglong2*)&sW[k][cg * CPT + j2 * 4];
                w2[2 * j2] = wv.x;
                w2[2 * j2 + 1] = wv.y;
            }
#pragma unroll
            for (int rr = 0; rr < 8; rr++) {
                ull xx = pack2(x[rr], x[rr]);
#pragma unroll
                for (int j = 0; j < NC2; j++)
                    acc[rr][j] = fma2(xx, w2[j], acc[rr][j]);
            }
        }
        __syncthreads();
    }

#pragma unroll
    for (int rr = 0; rr < 8; rr++) {
        int row = row0 + rg * 8 + rr;
        if (row < nrows) {
            ull* Yp = (ull*)(Y + (size_t)row * C + cg * CPT);
#pragma unroll
            for (int j2 = 0; j2 < NC2 / 2; j2++) {
                ulonglong2 o;
                o.x = acc[rr][2 * j2];
                o.y = acc[rr][2 * j2 + 1];
                *(ulonglong2*)(Yp + 2 * j2) = o;
            }
            unsigned hp[NC2];
#pragma unroll
            for (int j = 0; j < NC2; j++) {
                float lo = __uint_as_float((unsigned)acc[rr][j]);
                float hi = __uint_as_float((unsigned)(acc[rr][j] >> 32));
                __half2 h2 = __floats2half2_rn(lo, hi);
                hp[j] = *(unsigned*)&h2;
            }
            __half* Yhp = Yh + (size_t)row * C + cg * CPT;
            if (NC2 == 4) {
                uint4 o4;
                o4.x = hp[0]; o4.y = hp[1]; o4.z = hp[2]; o4.w = hp[3];
                *(uint4*)Yhp = o4;
            } else {
                uint2 o2;
                o2.x = hp[0]; o2.y = hp[1];
                *(uint2*)Yhp = o2;
            }
        }
    }
}

// ---------------- degree (int4 vectorized) ----------------
__global__ __launch_bounds__(256) void degree_kernel(
    const int* __restrict__ dst, int* __restrict__ deg)
{
    int e4 = blockIdx.x * blockDim.x + threadIdx.x;
    if (e4 < EE / 4) {
        int4 d = __ldg((const int4*)dst + e4);
        atomicAdd(deg + d.x, 1);
        atomicAdd(deg + d.y, 1);
        atomicAdd(deg + d.z, 1);
        atomicAdd(deg + d.w, 1);
    }
}

__global__ void dinv_kernel(const int* __restrict__ deg, float* __restrict__ dinv)
{
    int i = blockIdx.x * blockDim.x + threadIdx.x;
    if (i < NN) dinv[i] = rsqrtf(fmaxf((float)deg[i], 1.0f));
}

// ---------------- 3-kernel scan (deadlock-free under co-residency) --------
__global__ __launch_bounds__(1024) void scan_block(
    const int* __restrict__ deg, int* __restrict__ out, int* __restrict__ bsums)
{
    __shared__ int sh[1024];
    int i = blockIdx.x * 1024 + threadIdx.x;
    int v = (i < NN) ? deg[i] : 0;
    sh[threadIdx.x] = v;
    __syncthreads();
#pragma unroll
    for (int off = 1; off < 1024; off <<= 1) {
        int t = (threadIdx.x >= off) ? sh[threadIdx.x - off] : 0;
        __syncthreads();
        sh[threadIdx.x] += t;
        __syncthreads();
    }
    if (i < NN) out[i] = sh[threadIdx.x] - v;
    if (threadIdx.x == 1023) bsums[blockIdx.x] = sh[1023];
}

__global__ void scan_sums(int* __restrict__ bsums)
{
    if (threadIdx.x == 0) {
        int acc = 0;
        for (int i = 0; i < SCAN_BLKS; i++) {
            int t = bsums[i]; bsums[i] = acc; acc += t;
        }
    }
}

__global__ __launch_bounds__(1024) void scan_add(
    int* __restrict__ out, const int* __restrict__ bsums, int* __restrict__ cursor)
{
    int i = blockIdx.x * 1024 + threadIdx.x;
    if (i < NN) {
        int v = out[i] + bsums[blockIdx.x];
        out[i] = v;
        cursor[i] = v;
    }
}

// ---------------- fill CSR (packed 8B entries) ----------------
__global__ __launch_bounds__(256) void fill_csr(
    const int* __restrict__ src, const int* __restrict__ dst,
    const float* __restrict__ dinv, int* __restrict__ cursor,
    ull* __restrict__ csr)
{
    int e = blockIdx.x * blockDim.x + threadIdx.x;
    if (e >= EE) return;
    int s = __ldg(src + e);
    int d = __ldg(dst + e);
    int pos = atomicAdd(cursor + d, 1);
    float norm = __ldg(dinv + s) * __ldg(dinv + d);
    csr[pos] = (ull)(unsigned)s | ((ull)__float_as_uint(norm) << 32);
}

// ---------------- fused gather(fp16 neighbors) + combine + BN stats --------
template <int C>
__global__ __launch_bounds__(256) void gather_combine(
    const float* __restrict__ h, const __half* __restrict__ hh,
    const ull* __restrict__ csr,
    const int* __restrict__ row_start, const int* __restrict__ deg,
    const float* __restrict__ gammaArr, int r,
    float* __restrict__ x, float* __restrict__ stats)
{
    constexpr int GPN = C / 4;
    constexpr int NPB = 256 / GPN;
    __shared__ float sstats[2 * C];
    int tid = threadIdx.x;
    for (int i = tid; i < 2 * C; i += 256) sstats[i] = 0.f;
    __syncthreads();

    int g = tid & (GPN - 1);
    int node = blockIdx.x * NPB + tid / GPN;
    unsigned gmask = ((1u << GPN) - 1u) << ((tid & 31) & ~(GPN - 1));

    if (node < NN) {
        float gamma = __ldg(gammaArr + r);
        float og = 1.0f - gamma;
        int start = __ldg(row_start + node);
        int d = __ldg(deg + node);
        float4 acc = make_float4(0.f, 0.f, 0.f, 0.f);

        for (int base = 0; base < d; base += GPN) {
            int cnt = min(GPN, d - base);
            ull p = 0;
            if (g < cnt) p = __ldg(csr + start + base + g);
            if (cnt == GPN) {
#pragma unroll
                for (int j = 0; j < GPN; j++) {
                    ull pj = __shfl_sync(gmask, p, j, GPN);
                    int s = (int)(unsigned)pj;
                    float n = __uint_as_float((unsigned)(pj >> 32));
                    uint2 hv2 = __ldg((const uint2*)(hh + (size_t)s * C) + g);
                    float2 fa = __half22float2(*(__half2*)&hv2.x);
                    float2 fb = __half22float2(*(__half2*)&hv2.y);
                    acc.x = fmaf(n, fa.x, acc.x);
                    acc.y = fmaf(n, fa.y, acc.y);
                    acc.z = fmaf(n, fb.x, acc.z);
                    acc.w = fmaf(n, fb.y, acc.w);
                }
            } else {
                for (int j = 0; j < cnt; j++) {
                    ull pj = __shfl_sync(gmask, p, j, GPN);
                    int s = (int)(unsigned)pj;
                    float n = __uint_as_float((unsigned)(pj >> 32));
                    uint2 hv2 = __ldg((const uint2*)(hh + (size_t)s * C) + g);
                    float2 fa = __half22float2(*(__half2*)&hv2.x);
                    float2 fb = __half22float2(*(__half2*)&hv2.y);
                    acc.x = fmaf(n, fa.x, acc.x);
                    acc.y = fmaf(n, fa.y, acc.y);
                    acc.z = fmaf(n, fb.x, acc.z);
                    acc.w = fmaf(n, fb.y, acc.w);
                }
            }
        }

        float4 hv = __ldg((const float4*)(h + (size_t)node * C) + g);
        float4 xv;
        xv.x = fmaf(gamma, acc.x, og * hv.x);
        xv.y = fmaf(gamma, acc.y, og * hv.y);
        xv.z = fmaf(gamma, acc.z, og * hv.z);
        xv.w = fmaf(gamma, acc.w, og * hv.w);
        ((float4*)(x + (size_t)node * C))[g] = xv;

        int c0 = g * 4;
        atomicAdd(&sstats[c0 + 0], xv.x);
        atomicAdd(&sstats[c0 + 1], xv.y);
        atomicAdd(&sstats[c0 + 2], xv.z);
        atomicAdd(&sstats[c0 + 3], xv.w);
        atomicAdd(&sstats[C + c0 + 0], xv.x * xv.x);
        atomicAdd(&sstats[C + c0 + 1], xv.y * xv.y);
        atomicAdd(&sstats[C + c0 + 2], xv.z * xv.z);
        atomicAdd(&sstats[C + c0 + 3], xv.w * xv.w);
    }
    __syncthreads();
    for (int i = tid; i < 2 * C; i += 256) atomicAdd(&stats[i], sstats[i]);
}

// ---------------- fold BN into affine (a,b) ----------------
template <int C>
__global__ void finalize_bn(const float* __restrict__ stats,
                            const float* __restrict__ scale,
                            const float* __restrict__ bias,
                            float* __restrict__ bn)
{
    int c = threadIdx.x;
    float mean = stats[c] * (1.0f / NN);
    float var = stats[C + c] * (1.0f / NN) - mean * mean;
    float inv = rsqrtf(var + 1e-5f);
    float a = __ldg(scale + c) * inv;
    bn[c] = a;
    bn[C + c] = __ldg(bias + c) - mean * a;
}

// ---------------- gather batch nodes + BN2 + relu + log_softmax ------------
__global__ __launch_bounds__(256) void out_kernel(
    const float* __restrict__ x2, const int* __restrict__ bnodes,
    const float* __restrict__ bn, float* __restrict__ out, int r)
{
    int idx = blockIdx.x * blockDim.x + threadIdx.x;
    int b = idx >> 5;
    int lane = idx & 31;
    if (b >= BB) return;
    int node = __ldg(bnodes + b);
    float v = x2[(size_t)node * OO + lane];
    v = fmaxf(0.f, fmaf(v, bn[lane], bn[OO + lane]));
    float m = v;
#pragma unroll
    for (int o = 16; o; o >>= 1) m = fmaxf(m, __shfl_xor_sync(0xffffffffu, m, o));
    float e = expf(v - m);
    float ssum = e;
#pragma unroll
    for (int o = 16; o; o >>= 1) ssum += __shfl_xor_sync(0xffffffffu, ssum, o);
    out[(size_t)b * (RR * OO) + r * OO + lane] = v - m - logf(ssum);
}

// ---------------- launcher ----------------
static void build_csr_rel(int r, int b, const int* edge_index,
                          void* p_bb, void* p_rows2, void* p_csr2,
                          void* p_dinv, void* p_cur, void* p_bs,
                          cudaStream_t s)
{
    const int* src = edge_index + (size_t)r * 2 * EE;
    const int* dst = src + EE;
    int* deg  = (int*)((char*)p_bb + (size_t)b * sizeof(BuildBuf));
    int* rows = (int*)((char*)p_rows2 + (size_t)b * NN * sizeof(int));
    ull* csr  = (ull*)((char*)p_csr2 + (size_t)b * EE * sizeof(ull));

    cudaMemsetAsync(deg, 0, NN * sizeof(int), s);
    degree_kernel<<<(EE / 4 + 255) / 256, 256, 0, s>>>(dst, deg);
    dinv_kernel<<<(NN + 255) / 256, 256, 0, s>>>(deg, (float*)p_dinv);
    scan_block<<<SCAN_BLKS, 1024, 0, s>>>(deg, rows, (int*)p_bs);
    scan_sums<<<1, 32, 0, s>>>((int*)p_bs);
    scan_add<<<SCAN_BLKS, 1024, 0, s>>>(rows, (const int*)p_bs, (int*)p_cur);
    fill_csr<<<(EE + 255) / 256, 256, 0, s>>>(src, dst, (const float*)p_dinv,
                                              (int*)p_cur, csr);
}

extern "C" void kernel_launch(void* const* d_in, const int* in_sizes, int n_in,
                              void* d_out, int out_size)
{
    const float* features    = (const float*)d_in[0];
    const int*   edge_index  = (const int*)d_in[1];
    const int*   batch_nodes = (const int*)d_in[2];
    const float* W1 = (const float*)d_in[3];
    const float* b1 = (const float*)d_in[4];
    const float* W2 = (const float*)d_in[5];
    const float* b2 = (const float*)d_in[6];
    const float* gamma1 = (const float*)d_in[7];
    const float* gamma2 = (const float*)d_in[8];
    const float* bn1s = (const float*)d_in[9];
    const float* bn1b = (const float*)d_in[10];
    const float* bn2s = (const float*)d_in[11];
    const float* bn2b = (const float*)d_in[12];
    float* out = (float*)d_out;

    static cudaStream_t sB = nullptr, sC = nullptr;
    static cudaEvent_t e_fork, evC[RR], evH[RR], evD0, evG0;
    if (sB == nullptr) {
        cudaStreamCreateWithFlags(&sB, cudaStreamNonBlocking);
        cudaStreamCreateWithFlags(&sC, cudaStreamNonBlocking);
        cudaEventCreateWithFlags(&e_fork, cudaEventDisableTiming);
        cudaEventCreateWithFlags(&evD0, cudaEventDisableTiming);
        cudaEventCreateWithFlags(&evG0, cudaEventDisableTiming);
        for (int i = 0; i < RR; i++) {
            cudaEventCreateWithFlags(&evC[i], cudaEventDisableTiming);
            cudaEventCreateWithFlags(&evH[i], cudaEventDisableTiming);
        }
    }

    void *p_bb, *p_rows2, *p_csr2, *p_dinv, *p_cur, *p_bs,
         *p_h1b, *p_h1hb, *p_x1, *p_h2, *p_h2h, *p_x2, *p_stats, *p_bn;
    cudaGetSymbolAddress(&p_bb, g_bb);
    cudaGetSymbolAddress(&p_rows2, g_rowstart2);
    cudaGetSymbolAddress(&p_csr2, g_csr2);
    cudaGetSymbolAddress(&p_dinv, g_dinv);
    cudaGetSymbolAddress(&p_cur, g_cursor);
    cudaGetSymbolAddress(&p_bs, g_bsums);
    cudaGetSymbolAddress(&p_h1b, g_h1b);
    cudaGetSymbolAddress(&p_h1hb, g_h1hb);
    cudaGetSymbolAddress(&p_x1, g_x1);
    cudaGetSymbolAddress(&p_h2, g_h2);
    cudaGetSymbolAddress(&p_h2h, g_h2h);
    cudaGetSymbolAddress(&p_x2, g_x2);
    cudaGetSymbolAddress(&p_stats, g_stats);
    cudaGetSymbolAddress(&p_bn, g_bn);

    const int GEMM_GRID = (NN + 255) / 256;

    auto h1f = [&](int b) {
        return (float*)((char*)p_h1b + (size_t)b * NN * HH * sizeof(float));
    };
    auto h1h = [&](int b) {
        return (__half*)((char*)p_h1hb + (size_t)b * NN * HH * sizeof(__half));
    };

    // fork build + gemm1 streams off the capture stream
    cudaEventRecord(e_fork, 0);
    cudaStreamWaitEvent(sB, e_fork, 0);
    cudaStreamWaitEvent(sC, e_fork, 0);

    // builds 0 and 1 on sB (independent buffers)
    build_csr_rel(0, 0, edge_index, p_bb, p_rows2, p_csr2, p_dinv, p_cur, p_bs, sB);
    cudaEventRecord(evC[0], sB);
    build_csr_rel(1, 1, edge_index, p_bb, p_rows2, p_csr2, p_dinv, p_cur, p_bs, sB);
    cudaEventRecord(evC[1], sB);

    // gemm1 for relations 0 and 1 on sC (independent h1 buffers)
    gemm_tiled<FF, HH, false><<<GEMM_GRID, 256, 0, sC>>>(
        features, W1 + (size_t)0 * FF * HH, b1 + 0 * HH, nullptr,
        h1f(0), h1h(0), NN);
    cudaEventRecord(evH[0], sC);
    gemm_tiled<FF, HH, false><<<GEMM_GRID, 256, 0, sC>>>(
        features, W1 + (size_t)1 * FF * HH, b1 + 1 * HH, nullptr,
        h1f(1), h1h(1), NN);
    cudaEventRecord(evH[1], sC);

    for (int r = 0; r < RR; r++) {
        int b = r & 1;
        int* deg  = (int*)((char*)p_bb + (size_t)b * sizeof(BuildBuf));
        int* rows = (int*)((char*)p_rows2 + (size_t)b * NN * sizeof(int));
        ull* csr  = (ull*)((char*)p_csr2 + (size_t)b * EE * sizeof(ull));

        cudaStreamWaitEvent(0, evH[r], 0);
        cudaStreamWaitEvent(0, evC[r], 0);
        cudaMemsetAsync(p_stats, 0, 2 * HH * sizeof(float), 0);

        gather_combine<HH><<<(NN + 15) / 16, 256>>>(
            h1f(b), h1h(b), (const ull*)csr,
            (const int*)rows, deg, gamma1, r,
            (float*)p_x1, (float*)p_stats);

        if (r == 0) {
            // h1 buffer 0 free after gather1(0): start gemm1(2) on sC now.
            cudaEventRecord(evD0, 0);
            cudaStreamWaitEvent(sC, evD0, 0);
            gemm_tiled<FF, HH, false><<<GEMM_GRID, 256, 0, sC>>>(
                features, W1 + (size_t)2 * FF * HH, b1 + 2 * HH, nullptr,
                h1f(0), h1h(0), NN);
            cudaEventRecord(evH[2], sC);
        }

        finalize_bn<HH><<<1, HH>>>((const float*)p_stats, bn1s + r * HH,
                                   bn1b + r * HH, (float*)p_bn);

        gemm_tiled<HH, OO, true><<<GEMM_GRID, 256>>>(
            (const float*)p_x1, W2 + (size_t)r * HH * OO, b2 + r * OO,
            (const float*)p_bn, (float*)p_h2, (__half*)p_h2h, NN);

        cudaMemsetAsync(p_stats, 0, 2 * OO * sizeof(float), 0);
        gather_combine<OO><<<(NN + 31) / 32, 256>>>(
            (const float*)p_h2, (const __half*)p_h2h, (const ull*)csr,
            (const int*)rows, deg, gamma2, r,
            (float*)p_x2, (float*)p_stats);
        finalize_bn<OO><<<1, OO>>>((const float*)p_stats, bn2s + r * OO,
                                   bn2b + r * OO, (float*)p_bn);

        out_kernel<<<(BB * 32 + 255) / 256, 256>>>(
            (const float*)p_x2, batch_nodes, (const float*)p_bn, out, r);

        if (r == 0) {
            // csr buffer 0's last consumer enqueued: release for build 2.
            cudaEventRecord(evG0, 0);
            cudaStreamWaitEvent(sB, evG0, 0);
            build_csr_rel(2, 0, edge_index, p_bb, p_rows2, p_csr2,
                          p_dinv, p_cur, p_bs, sB);
            cudaEventRecord(evC[2], sB);
        }
    }
}

// round 13
// speedup vs baseline: 1.0702x; 1.0702x over previous
#include <cuda_runtime.h>
#include <cuda_fp16.h>

#define NN 100000
#define EE 1600000
#define RR 3
#define FF 128
#define HH 64
#define OO 32
#define BB 50000
#define SCAN_BLKS ((NN + 1023) / 1024)
#define NPAD 100096            // 1564 * 64, padded row count for mma tiles

typedef unsigned long long ull;

// ---------------- scratch ----------------
struct BuildBuf { int deg[NN]; };
__device__ BuildBuf g_bb[2];
__device__ int    g_rowstart2[2][NN];
__device__ ull    g_csr2[2][EE];
__device__ float  g_dinv[NN];
__device__ int    g_cursor[NN];
__device__ int    g_bsums[SCAN_BLKS];
__device__ __half g_feat_h[(size_t)NPAD * FF];   // fp16 features (padded, zero tail)
__device__ __half g_W1h[RR * FF * HH];           // fp16 conv1 weights
__device__ float  g_h1[NN * HH];
__device__ __half g_h1h[NN * HH];
__device__ float  g_x1[NN * HH];
__device__ float  g_h2[NN * OO];
__device__ __half g_h2h[NN * OO];
__device__ float  g_x2[NN * OO];
__device__ float  g_stats[2 * HH];
__device__ float  g_bn[2 * HH];

// ---------------- f32x2 helpers ----------------
__device__ __forceinline__ ull fma2(ull a, ull b, ull c)
{
    ull d;
    asm("fma.rn.f32x2 %0, %1, %2, %3;" : "=l"(d) : "l"(a), "l"(b), "l"(c));
    return d;
}
__device__ __forceinline__ ull pack2(float x, float y)
{
    ull d;
    asm("mov.b64 %0, {%1,%2};" : "=l"(d) : "f"(x), "f"(y));
    return d;
}

// ---------------- mma helpers ----------------
__device__ __forceinline__ void ldsm4(unsigned& d0, unsigned& d1,
                                      unsigned& d2, unsigned& d3, unsigned addr)
{
    asm volatile("ldmatrix.sync.aligned.m8n8.x4.shared.b16 {%0,%1,%2,%3}, [%4];"
                 : "=r"(d0), "=r"(d1), "=r"(d2), "=r"(d3) : "r"(addr));
}
__device__ __forceinline__ void ldsm4t(unsigned& d0, unsigned& d1,
                                       unsigned& d2, unsigned& d3, unsigned addr)
{
    asm volatile("ldmatrix.sync.aligned.m8n8.x4.trans.shared.b16 {%0,%1,%2,%3}, [%4];"
                 : "=r"(d0), "=r"(d1), "=r"(d2), "=r"(d3) : "r"(addr));
}
__device__ __forceinline__ void mma16816(float* c,
    unsigned a0, unsigned a1, unsigned a2, unsigned a3,
    unsigned b0, unsigned b1)
{
    asm volatile(
        "mma.sync.aligned.m16n8k16.row.col.f32.f16.f16.f32 "
        "{%0,%1,%2,%3}, {%4,%5,%6,%7}, {%8,%9}, {%0,%1,%2,%3};"
        : "+f"(c[0]), "+f"(c[1]), "+f"(c[2]), "+f"(c[3])
        : "r"(a0), "r"(a1), "r"(a2), "r"(a3), "r"(b0), "r"(b1));
}

// ---------------- fp16 conversion kernels ----------------
__global__ __launch_bounds__(256) void cvt_feat(const float* __restrict__ f)
{
    int i = blockIdx.x * blockDim.x + threadIdx.x;     // per 4 floats
    if (i >= NPAD * FF / 4) return;
    float4 v = make_float4(0.f, 0.f, 0.f, 0.f);
    if (i < NN * FF / 4) v = __ldg((const float4*)f + i);
    __half2 h0 = __floats2half2_rn(v.x, v.y);
    __half2 h1 = __floats2half2_rn(v.z, v.w);
    uint2 o;
    o.x = *(unsigned*)&h0;
    o.y = *(unsigned*)&h1;
    *(uint2*)(g_feat_h + (size_t)i * 4) = o;
}

__global__ __launch_bounds__(256) void cvt_w(const float* __restrict__ W1)
{
    int i = blockIdx.x * blockDim.x + threadIdx.x;
    if (i >= RR * FF * HH / 4) return;
    float4 v = __ldg((const float4*)W1 + i);
    __half2 h0 = __floats2half2_rn(v.x, v.y);
    __half2 h1 = __floats2half2_rn(v.z, v.w);
    uint2 o;
    o.x = *(unsigned*)&h0;
    o.y = *(unsigned*)&h1;
    *(uint2*)(g_W1h + (size_t)i * 4) = o;
}

// ---------------- conv1 GEMM via HMMA: h1[M,64] = Xh @ Wh + b ----------------
// Block: 128 threads = 4 warps; tile M=64 (16 rows/warp), N=64, K=128 in one stage.
#define XS 136   // X smem stride in fp16 (128 + 8 pad; 16B-aligned rows)
#define WS 72    // W smem stride in fp16 (64 + 8 pad)
__global__ __launch_bounds__(128) void gemm1_mma(
    const __half* __restrict__ Xh, const __half* __restrict__ Wh,
    const float* __restrict__ bg,
    float* __restrict__ Y, __half* __restrict__ Yh, int nrows)
{
    __shared__ __half sX[64 * XS];
    __shared__ __half sW[FF * WS];
    int tid = threadIdx.x;
    int wid = tid >> 5, lane = tid & 31;
    int row0 = blockIdx.x * 64;

    // stage W [128 x 64] fp16 (row k contiguous): 8 uint4 per row
    for (int i = tid; i < FF * 8; i += 128) {
        int rk = i >> 3, c = i & 7;
        uint4 v = __ldg((const uint4*)(Wh + (size_t)rk * HH) + c);
        *(uint4*)(sW + rk * WS + c * 8) = v;
    }
    // stage X tile [64 x 128] fp16: 16 uint4 per row
    for (int i = tid; i < 64 * 16; i += 128) {
        int rr = i >> 4, c = i & 15;
        uint4 v = __ldg((const uint4*)(Xh + (size_t)(row0 + rr) * FF) + c);
        *(uint4*)(sX + rr * XS + c * 8) = v;
    }
    __syncthreads();

    float acc[8][4];
#pragma unroll
    for (int j = 0; j < 8; j++)
#pragma unroll
        for (int q = 0; q < 4; q++) acc[j][q] = 0.f;

    int m = lane >> 3, r7 = lane & 7;
#pragma unroll
    for (int ks = 0; ks < 8; ks++) {
        unsigned a0, a1, a2, a3;
        unsigned aaddr = (unsigned)__cvta_generic_to_shared(
            sX + (16 * wid + (m & 1) * 8 + r7) * XS + ks * 16 + (m >> 1) * 8);
        ldsm4(a0, a1, a2, a3, aaddr);
#pragma unroll
        for (int jp = 0; jp < 4; jp++) {
            unsigned b0, b1, b2, b3;
            unsigned baddr = (unsigned)__cvta_generic_to_shared(
                sW + (ks * 16 + (m & 1) * 8 + r7) * WS + jp * 16 + (m >> 1) * 8);
            ldsm4t(b0, b1, b2, b3, baddr);
            mma16816(acc[2 * jp],     a0, a1, a2, a3, b0, b1);
            mma16816(acc[2 * jp + 1], a0, a1, a2, a3, b2, b3);
        }
    }

    // epilogue: add bias, write fp32 + fp16 sidecar
    int rbase = row0 + 16 * wid + (lane >> 2);
    int cb = (lane & 3) * 2;
#pragma unroll
    for (int j = 0; j < 8; j++) {
        int col = j * 8 + cb;
        float bx = __ldg(bg + col), by = __ldg(bg + col + 1);
        float v0 = acc[j][0] + bx, v1 = acc[j][1] + by;
        float v2 = acc[j][2] + bx, v3 = acc[j][3] + by;
        if (rbase < nrows) {
            *(float2*)(Y + (size_t)rbase * HH + col) = make_float2(v0, v1);
            __half2 h = __floats2half2_rn(v0, v1);
            *(unsigned*)(Yh + (size_t)rbase * HH + col) = *(unsigned*)&h;
        }
        if (rbase + 8 < nrows) {
            *(float2*)(Y + (size_t)(rbase + 8) * HH + col) = make_float2(v2, v3);
            __half2 h = __floats2half2_rn(v2, v3);
            *(unsigned*)(Yh + (size_t)(rbase + 8) * HH + col) = *(unsigned*)&h;
        }
    }
}

// ---------------- tiled GEMM (f32x2) for conv2 ----------------
template <int K, int C, bool FUSE>
__global__ __launch_bounds__(256, 2) void gemm_tiled(
    const float* __restrict__ X, const float* __restrict__ Wg,
    const float* __restrict__ bg, const float* __restrict__ bnp,
    float* __restrict__ Y, __half* __restrict__ Yh, int nrows)
{
    constexpr int KB = 32;
    constexpr int CPT = C / 8;
    constexpr int NC2 = CPT / 2;
    __shared__ float sXT[KB][256];
    __shared__ float sW[KB][C];

    int tid = threadIdx.x;
    int rg = tid >> 3;
    int cg = tid & 7;
    int row0 = blockIdx.x * 256;
    int myrow = row0 + tid;
    bool valid = myrow < nrows;

    ull acc[8][NC2];
    {
        const ull* bp = (const ull*)(bg + cg * CPT);
#pragma unroll
        for (int j = 0; j < NC2; j++) {
            ull bv = __ldg(bp + j);
#pragma unroll
            for (int rr = 0; rr < 8; rr++) acc[rr][j] = bv;
        }
    }

    const float4* Xr = (const float4*)(X + (size_t)myrow * K);

    for (int kc = 0; kc < K; kc += KB) {
        {
            const float4* Wt = (const float4*)(Wg + (size_t)kc * C);
#pragma unroll
            for (int i = tid; i < KB * C / 4; i += 256)
                ((float4*)&sW[0][0])[i] = __ldg(Wt + i);
        }
#pragma unroll
        for (int j4 = 0; j4 < KB / 4; j4++) {
            float4 v = valid ? __ldg(Xr + kc / 4 + j4)
                             : make_float4(0.f, 0.f, 0.f, 0.f);
            if (FUSE) {
                float4 a = __ldg((const float4*)bnp + kc / 4 + j4);
                float4 b = __ldg((const float4*)(bnp + K) + kc / 4 + j4);
                v.x = fmaxf(0.f, fmaf(v.x, a.x, b.x));
                v.y = fmaxf(0.f, fmaf(v.y, a.y, b.y));
                v.z = fmaxf(0.f, fmaf(v.z, a.z, b.z));
                v.w = fmaxf(0.f, fmaf(v.w, a.w, b.w));
            }
            sXT[j4 * 4 + 0][tid] = v.x;
            sXT[j4 * 4 + 1][tid] = v.y;
            sXT[j4 * 4 + 2][tid] = v.z;
            sXT[j4 * 4 + 3][tid] = v.w;
        }
        __syncthreads();

#pragma unroll
        for (int k = 0; k < KB; k++) {
            float x[8];
            *(float4*)&x[0] = *(const float4*)&sXT[k][rg * 8];
            *(float4*)&x[4] = *(const float4*)&sXT[k][rg * 8 + 4];
            ull w2[NC2];
#pragma unroll
            for (int j2 = 0; j2 < NC2 / 2; j2++) {
                ulonglong2 wv = *(const ulonglong2*)&sW[k][cg * CPT + j2 * 4];
                w2[2 * j2] = wv.x;
                w2[2 * j2 + 1] = wv.y;
            }
#pragma unroll
            for (int rr = 0; rr < 8; rr++) {
                ull xx = pack2(x[rr], x[rr]);
#pragma unroll
                for (int j = 0; j < NC2; j++)
                    acc[rr][j] = fma2(xx, w2[j], acc[rr][j]);
            }
        }
        __syncthreads();
    }

#pragma unroll
    for (int rr = 0; rr < 8; rr++) {
        int row = row0 + rg * 8 + rr;
        if (row < nrows) {
            ull* Yp = (ull*)(Y + (size_t)row * C + cg * CPT);
#pragma unroll
            for (int j2 = 0; j2 < NC2 / 2; j2++) {
                ulonglong2 o;
                o.x = acc[rr][2 * j2];
                o.y = acc[rr][2 * j2 + 1];
                *(ulonglong2*)(Yp + 2 * j2) = o;
            }
            unsigned hp[NC2];
#pragma unroll
            for (int j = 0; j < NC2; j++) {
                float lo = __uint_as_float((unsigned)acc[rr][j]);
                float hi = __uint_as_float((unsigned)(acc[rr][j] >> 32));
                __half2 h2 = __floats2half2_rn(lo, hi);
                hp[j] = *(unsigned*)&h2;
            }
            __half* Yhp = Yh + (size_t)row * C + cg * CPT;
            uint2 o2;
            o2.x = hp[0]; o2.y = hp[1];
            *(uint2*)Yhp = o2;
        }
    }
}

// ---------------- degree (int4 vectorized) ----------------
__global__ __launch_bounds__(256) void degree_kernel(
    const int* __restrict__ dst, int* __restrict__ deg)
{
    int e4 = blockIdx.x * blockDim.x + threadIdx.x;
    if (e4 < EE / 4) {
        int4 d = __ldg((const int4*)dst + e4);
        atomicAdd(deg + d.x, 1);
        atomicAdd(deg + d.y, 1);
        atomicAdd(deg + d.z, 1);
        atomicAdd(deg + d.w, 1);
    }
}

// ---------------- scan stage 1 (+ fused dinv) ----------------
__global__ __launch_bounds__(1024) void scan_block(
    const int* __restrict__ deg, int* __restrict__ out,
    int* __restrict__ bsums, float* __restrict__ dinv)
{
    __shared__ int sh[1024];
    int i = blockIdx.x * 1024 + threadIdx.x;
    int v = (i < NN) ? deg[i] : 0;
    if (i < NN) dinv[i] = rsqrtf(fmaxf((float)v, 1.0f));
    sh[threadIdx.x] = v;
    __syncthreads();
#pragma unroll
    for (int off = 1; off < 1024; off <<= 1) {
        int t = (threadIdx.x >= off) ? sh[threadIdx.x - off] : 0;
        __syncthreads();
        sh[threadIdx.x] += t;
        __syncthreads();
    }
    if (i < NN) out[i] = sh[threadIdx.x] - v;
    if (threadIdx.x == 1023) bsums[blockIdx.x] = sh[1023];
}

__global__ void scan_sums(int* __restrict__ bsums)
{
    if (threadIdx.x == 0) {
        int acc = 0;
        for (int i = 0; i < SCAN_BLKS; i++) {
            int t = bsums[i]; bsums[i] = acc; acc += t;
        }
    }
}

__global__ __launch_bounds__(1024) void scan_add(
    int* __restrict__ out, const int* __restrict__ bsums, int* __restrict__ cursor)
{
    int i = blockIdx.x * 1024 + threadIdx.x;
    if (i < NN) {
        int v = out[i] + bsums[blockIdx.x];
        out[i] = v;
        cursor[i] = v;
    }
}

// ---------------- fill CSR (packed 8B entries) ----------------
__global__ __launch_bounds__(256) void fill_csr(
    const int* __restrict__ src, const int* __restrict__ dst,
    const float* __restrict__ dinv, int* __restrict__ cursor,
    ull* __restrict__ csr)
{
    int e = blockIdx.x * blockDim.x + threadIdx.x;
    if (e >= EE) return;
    int s = __ldg(src + e);
    int d = __ldg(dst + e);
    int pos = atomicAdd(cursor + d, 1);
    float norm = __ldg(dinv + s) * __ldg(dinv + d);
    csr[pos] = (ull)(unsigned)s | ((ull)__float_as_uint(norm) << 32);
}

// ---------------- fused gather(fp16 neighbors) + combine + BN stats --------
template <int C>
__global__ __launch_bounds__(256) void gather_combine(
    const float* __restrict__ h, const __half* __restrict__ hh,
    const ull* __restrict__ csr,
    const int* __restrict__ row_start, const int* __restrict__ deg,
    const float* __restrict__ gammaArr, int r,
    float* __restrict__ x, float* __restrict__ stats)
{
    constexpr int GPN = C / 4;
    constexpr int NPB = 256 / GPN;
    __shared__ float sstats[2 * C];
    int tid = threadIdx.x;
    for (int i = tid; i < 2 * C; i += 256) sstats[i] = 0.f;
    __syncthreads();

    int g = tid & (GPN - 1);
    int node = blockIdx.x * NPB + tid / GPN;
    unsigned gmask = ((1u << GPN) - 1u) << ((tid & 31) & ~(GPN - 1));

    if (node < NN) {
        float gamma = __ldg(gammaArr + r);
        float og = 1.0f - gamma;
        int start = __ldg(row_start + node);
        int d = __ldg(deg + node);
        float4 acc = make_float4(0.f, 0.f, 0.f, 0.f);

        for (int base = 0; base < d; base += GPN) {
            int cnt = min(GPN, d - base);
            ull p = 0;
            if (g < cnt) p = __ldg(csr + start + base + g);
            if (cnt == GPN) {
#pragma unroll
                for (int j = 0; j < GPN; j++) {
                    ull pj = __shfl_sync(gmask, p, j, GPN);
                    int s = (int)(unsigned)pj;
                    float n = __uint_as_float((unsigned)(pj >> 32));
                    uint2 hv2 = __ldg((const uint2*)(hh + (size_t)s * C) + g);
                    float2 fa = __half22float2(*(__half2*)&hv2.x);
                    float2 fb = __half22float2(*(__half2*)&hv2.y);
                    acc.x = fmaf(n, fa.x, acc.x);
                    acc.y = fmaf(n, fa.y, acc.y);
                    acc.z = fmaf(n, fb.x, acc.z);
                    acc.w = fmaf(n, fb.y, acc.w);
                }
            } else {
                for (int j = 0; j < cnt; j++) {
                    ull pj = __shfl_sync(gmask, p, j, GPN);
                    int s = (int)(unsigned)pj;
                    float n = __uint_as_float((unsigned)(pj >> 32));
                    uint2 hv2 = __ldg((const uint2*)(hh + (size_t)s * C) + g);
                    float2 fa = __half22float2(*(__half2*)&hv2.x);
                    float2 fb = __half22float2(*(__half2*)&hv2.y);
                    acc.x = fmaf(n, fa.x, acc.x);
                    acc.y = fmaf(n, fa.y, acc.y);
                    acc.z = fmaf(n, fb.x, acc.z);
                    acc.w = fmaf(n, fb.y, acc.w);
                }
            }
        }

        float4 hv = __ldg((const float4*)(h + (size_t)node * C) + g);
        float4 xv;
        xv.x = fmaf(gamma, acc.x, og * hv.x);
        xv.y = fmaf(gamma, acc.y, og * hv.y);
        xv.z = fmaf(gamma, acc.z, og * hv.z);
        xv.w = fmaf(gamma, acc.w, og * hv.w);
        ((float4*)(x + (size_t)node * C))[g] = xv;

        int c0 = g * 4;
        atomicAdd(&sstats[c0 + 0], xv.x);
        atomicAdd(&sstats[c0 + 1], xv.y);
        atomicAdd(&sstats[c0 + 2], xv.z);
        atomicAdd(&sstats[c0 + 3], xv.w);
        atomicAdd(&sstats[C + c0 + 0], xv.x * xv.x);
        atomicAdd(&sstats[C + c0 + 1], xv.y * xv.y);
        atomicAdd(&sstats[C + c0 + 2], xv.z * xv.z);
        atomicAdd(&sstats[C + c0 + 3], xv.w * xv.w);
    }
    __syncthreads();
    for (int i = tid; i < 2 * C; i += 256) atomicAdd(&stats[i], sstats[i]);
}

// ---------------- fold BN into affine (a,b) ----------------
template <int C>
__global__ void finalize_bn(const float* __restrict__ stats,
                            const float* __restrict__ scale,
                            const float* __restrict__ bias,
                            float* __restrict__ bn)
{
    int c = threadIdx.x;
    float mean = stats[c] * (1.0f / NN);
    float var = stats[C + c] * (1.0f / NN) - mean * mean;
    float inv = rsqrtf(var + 1e-5f);
    float a = __ldg(scale + c) * inv;
    bn[c] = a;
    bn[C + c] = __ldg(bias + c) - mean * a;
}

// ---------------- gather batch nodes + BN2 + relu + log_softmax ------------
__global__ __launch_bounds__(256) void out_kernel(
    const float* __restrict__ x2, const int* __restrict__ bnodes,
    const float* __restrict__ bn, float* __restrict__ out, int r)
{
    int idx = blockIdx.x * blockDim.x + threadIdx.x;
    int b = idx >> 5;
    int lane = idx & 31;
    if (b >= BB) return;
    int node = __ldg(bnodes + b);
    float v = x2[(size_t)node * OO + lane];
    v = fmaxf(0.f, fmaf(v, bn[lane], bn[OO + lane]));
    float m = v;
#pragma unroll
    for (int o = 16; o; o >>= 1) m = fmaxf(m, __shfl_xor_sync(0xffffffffu, m, o));
    float e = expf(v - m);
    float ssum = e;
#pragma unroll
    for (int o = 16; o; o >>= 1) ssum += __shfl_xor_sync(0xffffffffu, ssum, o);
    out[(size_t)b * (RR * OO) + r * OO + lane] = v - m - logf(ssum);
}

// ---------------- launcher ----------------
static void build_csr_rel(int r, int b, const int* edge_index,
                          void* p_bb, void* p_rows2, void* p_csr2,
                          void* p_dinv, void* p_cur, void* p_bs,
                          cudaStream_t s)
{
    const int* src = edge_index + (size_t)r * 2 * EE;
    const int* dst = src + EE;
    int* deg  = (int*)((char*)p_bb + (size_t)b * sizeof(BuildBuf));
    int* rows = (int*)((char*)p_rows2 + (size_t)b * NN * sizeof(int));
    ull* csr  = (ull*)((char*)p_csr2 + (size_t)b * EE * sizeof(ull));

    cudaMemsetAsync(deg, 0, NN * sizeof(int), s);
    degree_kernel<<<(EE / 4 + 255) / 256, 256, 0, s>>>(dst, deg);
    scan_block<<<SCAN_BLKS, 1024, 0, s>>>(deg, rows, (int*)p_bs, (float*)p_dinv);
    scan_sums<<<1, 32, 0, s>>>((int*)p_bs);
    scan_add<<<SCAN_BLKS, 1024, 0, s>>>(rows, (const int*)p_bs, (int*)p_cur);
    fill_csr<<<(EE + 255) / 256, 256, 0, s>>>(src, dst, (const float*)p_dinv,
                                              (int*)p_cur, csr);
}

extern "C" void kernel_launch(void* const* d_in, const int* in_sizes, int n_in,
                              void* d_out, int out_size)
{
    const float* features    = (const float*)d_in[0];
    const int*   edge_index  = (const int*)d_in[1];
    const int*   batch_nodes = (const int*)d_in[2];
    const float* W1 = (const float*)d_in[3];
    const float* b1 = (const float*)d_in[4];
    const float* W2 = (const float*)d_in[5];
    const float* b2 = (const float*)d_in[6];
    const float* gamma1 = (const float*)d_in[7];
    const float* gamma2 = (const float*)d_in[8];
    const float* bn1s = (const float*)d_in[9];
    const float* bn1b = (const float*)d_in[10];
    const float* bn2s = (const float*)d_in[11];
    const float* bn2b = (const float*)d_in[12];
    float* out = (float*)d_out;

    static cudaStream_t sB = nullptr;
    static cudaEvent_t e_fork, evC[RR], evG0;
    if (sB == nullptr) {
        cudaStreamCreateWithFlags(&sB, cudaStreamNonBlocking);
        cudaEventCreateWithFlags(&e_fork, cudaEventDisableTiming);
        cudaEventCreateWithFlags(&evG0, cudaEventDisableTiming);
        for (int i = 0; i < RR; i++)
            cudaEventCreateWithFlags(&evC[i], cudaEventDisableTiming);
    }

    void *p_bb, *p_rows2, *p_csr2, *p_dinv, *p_cur, *p_bs,
         *p_feath, *p_w1h, *p_h1, *p_h1h, *p_x1, *p_h2, *p_h2h, *p_x2,
         *p_stats, *p_bn;
    cudaGetSymbolAddress(&p_bb, g_bb);
    cudaGetSymbolAddress(&p_rows2, g_rowstart2);
    cudaGetSymbolAddress(&p_csr2, g_csr2);
    cudaGetSymbolAddress(&p_dinv, g_dinv);
    cudaGetSymbolAddress(&p_cur, g_cursor);
    cudaGetSymbolAddress(&p_bs, g_bsums);
    cudaGetSymbolAddress(&p_feath, g_feat_h);
    cudaGetSymbolAddress(&p_w1h, g_W1h);
    cudaGetSymbolAddress(&p_h1, g_h1);
    cudaGetSymbolAddress(&p_h1h, g_h1h);
    cudaGetSymbolAddress(&p_x1, g_x1);
    cudaGetSymbolAddress(&p_h2, g_h2);
    cudaGetSymbolAddress(&p_h2h, g_h2h);
    cudaGetSymbolAddress(&p_x2, g_x2);
    cudaGetSymbolAddress(&p_stats, g_stats);
    cudaGetSymbolAddress(&p_bn, g_bn);

    const int GEMM_GRID = (NN + 255) / 256;
    const int MMA_GRID  = NPAD / 64;   // 1564

    // fp16 conversions (features once, reused by all relations)
    cvt_feat<<<(NPAD * FF / 4 + 255) / 256, 256>>>(features);
    cvt_w<<<(RR * FF * HH / 4 + 255) / 256, 256>>>(W1);

    // fork build stream off the capture stream
    cudaEventRecord(e_fork, 0);
    cudaStreamWaitEvent(sB, e_fork, 0);

    build_csr_rel(0, 0, edge_index, p_bb, p_rows2, p_csr2, p_dinv, p_cur, p_bs, sB);
    cudaEventRecord(evC[0], sB);
    build_csr_rel(1, 1, edge_index, p_bb, p_rows2, p_csr2, p_dinv, p_cur, p_bs, sB);
    cudaEventRecord(evC[1], sB);

    for (int r = 0; r < RR; r++) {
        int b = r & 1;
        int* deg  = (int*)((char*)p_bb + (size_t)b * sizeof(BuildBuf));
        int* rows = (int*)((char*)p_rows2 + (size_t)b * NN * sizeof(int));
        ull* csr  = (ull*)((char*)p_csr2 + (size_t)b * EE * sizeof(ull));

        // conv1 via tensor cores (fp16 in, fp32 accum)
        gemm1_mma<<<MMA_GRID, 128>>>(
            (const __half*)p_feath, (const __half*)p_w1h + (size_t)r * FF * HH,
            b1 + r * HH, (float*)p_h1, (__half*)p_h1h, NN);

        cudaStreamWaitEvent(0, evC[r], 0);
        cudaMemsetAsync(p_stats, 0, 2 * HH * sizeof(float), 0);

        gather_combine<HH><<<(NN + 15) / 16, 256>>>(
            (const float*)p_h1, (const __half*)p_h1h, (const ull*)csr,
            (const int*)rows, deg, gamma1, r,
            (float*)p_x1, (float*)p_stats);
        finalize_bn<HH><<<1, HH>>>((const float*)p_stats, bn1s + r * HH,
                                   bn1b + r * HH, (float*)p_bn);

        gemm_tiled<HH, OO, true><<<GEMM_GRID, 256>>>(
            (const float*)p_x1, W2 + (size_t)r * HH * OO, b2 + r * OO,
            (const float*)p_bn, (float*)p_h2, (__half*)p_h2h, NN);

        cudaMemsetAsync(p_stats, 0, 2 * OO * sizeof(float), 0);
        gather_combine<OO><<<(NN + 31) / 32, 256>>>(
            (const float*)p_h2, (const __half*)p_h2h, (const ull*)csr,
            (const int*)rows, deg, gamma2, r,
            (float*)p_x2, (float*)p_stats);
        finalize_bn<OO><<<1, OO>>>((const float*)p_stats, bn2s + r * OO,
                                   bn2b + r * OO, (float*)p_bn);

        out_kernel<<<(BB * 32 + 255) / 256, 256>>>(
            (const float*)p_x2, batch_nodes, (const float*)p_bn, out, r);

        if (r == 0) {
            cudaEventRecord(evG0, 0);
            cudaStreamWaitEvent(sB, evG0, 0);
            build_csr_rel(2, 0, edge_index, p_bb, p_rows2, p_csr2,
                          p_dinv, p_cur, p_bs, sB);
            cudaEventRecord(evC[2], sB);
        }
    }
}

// round 15
// speedup vs baseline: 1.2777x; 1.1939x over previous
#include <cuda_runtime.h>
#include <cuda_fp16.h>

#define NN 100000
#define EE 1600000
#define RR 3
#define FF 128
#define HH 64
#define OO 32
#define BB 50000
#define SCAN_BLKS ((NN + 1023) / 1024)
#define NPAD 100096            // 1564 * 64, padded row count for mma tiles

typedef unsigned long long ull;

// ---------------- scratch (triple-buffered per relation) ----------------
__device__ int    g_deg[RR][NN];
__device__ int    g_rows[RR][NN];
__device__ ull    g_csr[RR][EE];     // packed (src:int low32, norm:float high32)
__device__ float  g_dinv[NN];        // build-internal (builds serialize on sB)
__device__ int    g_cursor[NN];
__device__ int    g_bsums[SCAN_BLKS];
__device__ __half g_feat_h[(size_t)NPAD * FF];
__device__ __half g_W1h[RR * FF * HH];
__device__ float  g_h1[RR][NN * HH];
__device__ __half g_h1h[RR][NN * HH];
__device__ float  g_x1[RR][NN * HH];
__device__ float  g_h2[RR][NN * OO];
__device__ __half g_h2h[RR][NN * OO];
__device__ float  g_x2[RR][NN * OO];
__device__ float  g_stats1[RR][2 * HH];
__device__ float  g_stats2[RR][2 * OO];

// ---------------- f32x2 helpers ----------------
__device__ __forceinline__ ull fma2(ull a, ull b, ull c)
{
    ull d;
    asm("fma.rn.f32x2 %0, %1, %2, %3;" : "=l"(d) : "l"(a), "l"(b), "l"(c));
    return d;
}
__device__ __forceinline__ ull pack2(float x, float y)
{
    ull d;
    asm("mov.b64 %0, {%1,%2};" : "=l"(d) : "f"(x), "f"(y));
    return d;
}

// ---------------- mma helpers ----------------
__device__ __forceinline__ void ldsm4(unsigned& d0, unsigned& d1,
                                      unsigned& d2, unsigned& d3, unsigned addr)
{
    asm volatile("ldmatrix.sync.aligned.m8n8.x4.shared.b16 {%0,%1,%2,%3}, [%4];"
                 : "=r"(d0), "=r"(d1), "=r"(d2), "=r"(d3) : "r"(addr));
}
__device__ __forceinline__ void ldsm4t(unsigned& d0, unsigned& d1,
                                       unsigned& d2, unsigned& d3, unsigned addr)
{
    asm volatile("ldmatrix.sync.aligned.m8n8.x4.trans.shared.b16 {%0,%1,%2,%3}, [%4];"
                 : "=r"(d0), "=r"(d1), "=r"(d2), "=r"(d3) : "r"(addr));
}
__device__ __forceinline__ void mma16816(float* c,
    unsigned a0, unsigned a1, unsigned a2, unsigned a3,
    unsigned b0, unsigned b1)
{
    asm volatile(
        "mma.sync.aligned.m16n8k16.row.col.f32.f16.f16.f32 "
        "{%0,%1,%2,%3}, {%4,%5,%6,%7}, {%8,%9}, {%0,%1,%2,%3};"
        : "+f"(c[0]), "+f"(c[1]), "+f"(c[2]), "+f"(c[3])
        : "r"(a0), "r"(a1), "r"(a2), "r"(a3), "r"(b0), "r"(b1));
}

// ---------------- fp16 conversion kernels ----------------
__global__ __launch_bounds__(256) void cvt_feat(const float* __restrict__ f)
{
    int i = blockIdx.x * blockDim.x + threadIdx.x;
    if (i >= NPAD * FF / 4) return;
    float4 v = make_float4(0.f, 0.f, 0.f, 0.f);
    if (i < NN * FF / 4) v = __ldg((const float4*)f + i);
    __half2 h0 = __floats2half2_rn(v.x, v.y);
    __half2 h1 = __floats2half2_rn(v.z, v.w);
    uint2 o;
    o.x = *(unsigned*)&h0;
    o.y = *(unsigned*)&h1;
    *(uint2*)(g_feat_h + (size_t)i * 4) = o;
}

__global__ __launch_bounds__(256) void cvt_w(const float* __restrict__ W1)
{
    int i = blockIdx.x * blockDim.x + threadIdx.x;
    if (i >= RR * FF * HH / 4) return;
    float4 v = __ldg((const float4*)W1 + i);
    __half2 h0 = __floats2half2_rn(v.x, v.y);
    __half2 h1 = __floats2half2_rn(v.z, v.w);
    uint2 o;
    o.x = *(unsigned*)&h0;
    o.y = *(unsigned*)&h1;
    *(uint2*)(g_W1h + (size_t)i * 4) = o;
}

// ---------------- conv1 GEMM via HMMA ----------------
#define XS 136
#define WS 72
__global__ __launch_bounds__(128) void gemm1_mma(
    const __half* __restrict__ Xh, const __half* __restrict__ Wh,
    const float* __restrict__ bg,
    float* __restrict__ Y, __half* __restrict__ Yh, int nrows)
{
    __shared__ __half sX[64 * XS];
    __shared__ __half sW[FF * WS];
    int tid = threadIdx.x;
    int wid = tid >> 5, lane = tid & 31;
    int row0 = blockIdx.x * 64;

    for (int i = tid; i < FF * 8; i += 128) {
        int rk = i >> 3, c = i & 7;
        uint4 v = __ldg((const uint4*)(Wh + (size_t)rk * HH) + c);
        *(uint4*)(sW + rk * WS + c * 8) = v;
    }
    for (int i = tid; i < 64 * 16; i += 128) {
        int rr = i >> 4, c = i & 15;
        uint4 v = __ldg((const uint4*)(Xh + (size_t)(row0 + rr) * FF) + c);
        *(uint4*)(sX + rr * XS + c * 8) = v;
    }
    __syncthreads();

    float acc[8][4];
#pragma unroll
    for (int j = 0; j < 8; j++)
#pragma unroll
        for (int q = 0; q < 4; q++) acc[j][q] = 0.f;

    int m = lane >> 3, r7 = lane & 7;
#pragma unroll
    for (int ks = 0; ks < 8; ks++) {
        unsigned a0, a1, a2, a3;
        unsigned aaddr = (unsigned)__cvta_generic_to_shared(
            sX + (16 * wid + (m & 1) * 8 + r7) * XS + ks * 16 + (m >> 1) * 8);
        ldsm4(a0, a1, a2, a3, aaddr);
#pragma unroll
        for (int jp = 0; jp < 4; jp++) {
            unsigned b0, b1, b2, b3;
            unsigned baddr = (unsigned)__cvta_generic_to_shared(
                sW + (ks * 16 + (m & 1) * 8 + r7) * WS + jp * 16 + (m >> 1) * 8);
            ldsm4t(b0, b1, b2, b3, baddr);
            mma16816(acc[2 * jp],     a0, a1, a2, a3, b0, b1);
            mma16816(acc[2 * jp + 1], a0, a1, a2, a3, b2, b3);
        }
    }

    int rbase = row0 + 16 * wid + (lane >> 2);
    int cb = (lane & 3) * 2;
#pragma unroll
    for (int j = 0; j < 8; j++) {
        int col = j * 8 + cb;
        float bx = __ldg(bg + col), by = __ldg(bg + col + 1);
        float v0 = acc[j][0] + bx, v1 = acc[j][1] + by;
        float v2 = acc[j][2] + bx, v3 = acc[j][3] + by;
        if (rbase < nrows) {
            *(float2*)(Y + (size_t)rbase * HH + col) = make_float2(v0, v1);
            __half2 h = __floats2half2_rn(v0, v1);
            *(unsigned*)(Yh + (size_t)rbase * HH + col) = *(unsigned*)&h;
        }
        if (rbase + 8 < nrows) {
            *(float2*)(Y + (size_t)(rbase + 8) * HH + col) = make_float2(v2, v3);
            __half2 h = __floats2half2_rn(v2, v3);
            *(unsigned*)(Yh + (size_t)(rbase + 8) * HH + col) = *(unsigned*)&h;
        }
    }
}

// ---------------- tiled GEMM (f32x2) for conv2, inline BN fold -------------
template <int K, int C, bool FUSE>
__global__ __launch_bounds__(256, 2) void gemm_tiled(
    const float* __restrict__ X, const float* __restrict__ Wg,
    const float* __restrict__ bg,
    const float* __restrict__ stats, const float* __restrict__ bnscale,
    const float* __restrict__ bnbias,
    float* __restrict__ Y, __half* __restrict__ Yh, int nrows)
{
    constexpr int KB = 32;
    constexpr int CPT = C / 8;
    constexpr int NC2 = CPT / 2;
    __shared__ float sXT[KB][256];
    __shared__ float sW[KB][C];
    __shared__ float sBN[2 * K];

    int tid = threadIdx.x;
    int rg = tid >> 3;
    int cg = tid & 7;
    int row0 = blockIdx.x * 256;
    int myrow = row0 + tid;
    bool valid = myrow < nrows;

    if (FUSE && tid < K) {
        float mean = __ldg(stats + tid) * (1.0f / NN);
        float var = __ldg(stats + K + tid) * (1.0f / NN) - mean * mean;
        float inv = rsqrtf(var + 1e-5f);
        float a = __ldg(bnscale + tid) * inv;
        sBN[tid] = a;
        sBN[K + tid] = __ldg(bnbias + tid) - mean * a;
    }

    ull acc[8][NC2];
    {
        const ull* bp = (const ull*)(bg + cg * CPT);
#pragma unroll
        for (int j = 0; j < NC2; j++) {
            ull bv = __ldg(bp + j);
#pragma unroll
            for (int rr = 0; rr < 8; rr++) acc[rr][j] = bv;
        }
    }
    if (FUSE) __syncthreads();

    const float4* Xr = (const float4*)(X + (size_t)myrow * K);

    for (int kc = 0; kc < K; kc += KB) {
        {
            const float4* Wt = (const float4*)(Wg + (size_t)kc * C);
#pragma unroll
            for (int i = tid; i < KB * C / 4; i += 256)
                ((float4*)&sW[0][0])[i] = __ldg(Wt + i);
        }
#pragma unroll
        for (int j4 = 0; j4 < KB / 4; j4++) {
            float4 v = valid ? __ldg(Xr + kc / 4 + j4)
                             : make_float4(0.f, 0.f, 0.f, 0.f);
            if (FUSE) {
                int k0 = kc + j4 * 4;
                v.x = fmaxf(0.f, fmaf(v.x, sBN[k0 + 0], sBN[K + k0 + 0]));
                v.y = fmaxf(0.f, fmaf(v.y, sBN[k0 + 1], sBN[K + k0 + 1]));
                v.z = fmaxf(0.f, fmaf(v.z, sBN[k0 + 2], sBN[K + k0 + 2]));
                v.w = fmaxf(0.f, fmaf(v.w, sBN[k0 + 3], sBN[K + k0 + 3]));
            }
            sXT[j4 * 4 + 0][tid] = v.x;
            sXT[j4 * 4 + 1][tid] = v.y;
            sXT[j4 * 4 + 2][tid] = v.z;
            sXT[j4 * 4 + 3][tid] = v.w;
        }
        __syncthreads();

#pragma unroll
        for (int k = 0; k < KB; k++) {
            float x[8];
            *(float4*)&x[0] = *(const float4*)&sXT[k][rg * 8];
            *(float4*)&x[4] = *(const float4*)&sXT[k][rg * 8 + 4];
            ull w2[NC2];
#pragma unroll
            for (int j2 = 0; j2 < NC2 / 2; j2++) {
                ulonglong2 wv = *(const ulonglong2*)&sW[k][cg * CPT + j2 * 4];
                w2[2 * j2] = wv.x;
                w2[2 * j2 + 1] = wv.y;
            }
#pragma unroll
            for (int rr = 0; rr < 8; rr++) {
                ull xx = pack2(x[rr], x[rr]);
#pragma unroll
                for (int j = 0; j < NC2; j++)
                    acc[rr][j] = fma2(xx, w2[j], acc[rr][j]);
            }
        }
        __syncthreads();
    }

#pragma unroll
    for (int rr = 0; rr < 8; rr++) {
        int row = row0 + rg * 8 + rr;
        if (row < nrows) {
            ull* Yp = (ull*)(Y + (size_t)row * C + cg * CPT);
#pragma unroll
            for (int j2 = 0; j2 < NC2 / 2; j2++) {
                ulonglong2 o;
                o.x = acc[rr][2 * j2];
                o.y = acc[rr][2 * j2 + 1];
                *(ulonglong2*)(Yp + 2 * j2) = o;
            }
            unsigned hp[NC2];
#pragma unroll
            for (int j = 0; j < NC2; j++) {
                float lo = __uint_as_float((unsigned)acc[rr][j]);
                float hi = __uint_as_float((unsigned)(acc[rr][j] >> 32));
                __half2 h2 = __floats2half2_rn(lo, hi);
                hp[j] = *(unsigned*)&h2;
            }
            __half* Yhp = Yh + (size_t)row * C + cg * CPT;
            uint2 o2;
            o2.x = hp[0]; o2.y = hp[1];
            *(uint2*)Yhp = o2;
        }
    }
}

// ---------------- CSR build kernels ----------------
__global__ __launch_bounds__(256) void degree_kernel(
    const int* __restrict__ dst, int* __restrict__ deg)
{
    int e4 = blockIdx.x * blockDim.x + threadIdx.x;
    if (e4 < EE / 4) {
        int4 d = __ldg((const int4*)dst + e4);
        atomicAdd(deg + d.x, 1);
        atomicAdd(deg + d.y, 1);
        atomicAdd(deg + d.z, 1);
        atomicAdd(deg + d.w, 1);
    }
}

__global__ __launch_bounds__(1024) void scan_block(
    const int* __restrict__ deg, int* __restrict__ out,
    int* __restrict__ bsums, float* __restrict__ dinv)
{
    __shared__ int sh[1024];
    int i = blockIdx.x * 1024 + threadIdx.x;
    int v = (i < NN) ? deg[i] : 0;
    if (i < NN) dinv[i] = rsqrtf(fmaxf((float)v, 1.0f));
    sh[threadIdx.x] = v;
    __syncthreads();
#pragma unroll
    for (int off = 1; off < 1024; off <<= 1) {
        int t = (threadIdx.x >= off) ? sh[threadIdx.x - off] : 0;
        __syncthreads();
        sh[threadIdx.x] += t;
        __syncthreads();
    }
    if (i < NN) out[i] = sh[threadIdx.x] - v;
    if (threadIdx.x == 1023) bsums[blockIdx.x] = sh[1023];
}

__global__ void scan_sums(int* __restrict__ bsums)
{
    if (threadIdx.x == 0) {
        int acc = 0;
        for (int i = 0; i < SCAN_BLKS; i++) {
            int t = bsums[i]; bsums[i] = acc; acc += t;
        }
    }
}

__global__ __launch_bounds__(1024) void scan_add(
    int* __restrict__ out, const int* __restrict__ bsums, int* __restrict__ cursor)
{
    int i = blockIdx.x * 1024 + threadIdx.x;
    if (i < NN) {
        int v = out[i] + bsums[blockIdx.x];
        out[i] = v;
        cursor[i] = v;
    }
}

__global__ __launch_bounds__(256) void fill_csr(
    const int* __restrict__ src, const int* __restrict__ dst,
    const float* __restrict__ dinv, int* __restrict__ cursor,
    ull* __restrict__ csr)
{
    int e = blockIdx.x * blockDim.x + threadIdx.x;
    if (e >= EE) return;
    int s = __ldg(src + e);
    int d = __ldg(dst + e);
    int pos = atomicAdd(cursor + d, 1);
    float norm = __ldg(dinv + s) * __ldg(dinv + d);
    csr[pos] = (ull)(unsigned)s | ((ull)__float_as_uint(norm) << 32);
}

// ---------------- fused gather(fp16) + combine + BN stats ----------------
template <int C>
__global__ __launch_bounds__(256) void gather_combine(
    const float* __restrict__ h, const __half* __restrict__ hh,
    const ull* __restrict__ csr,
    const int* __restrict__ row_start, const int* __restrict__ deg,
    const float* __restrict__ gammaArr, int r,
    float* __restrict__ x, float* __restrict__ stats)
{
    constexpr int GPN = C / 4;
    constexpr int NPB = 256 / GPN;
    __shared__ float sstats[2 * C];
    int tid = threadIdx.x;
    for (int i = tid; i < 2 * C; i += 256) sstats[i] = 0.f;
    __syncthreads();

    int g = tid & (GPN - 1);
    int node = blockIdx.x * NPB + tid / GPN;
    unsigned gmask = ((1u << GPN) - 1u) << ((tid & 31) & ~(GPN - 1));

    if (node < NN) {
        float gamma = __ldg(gammaArr + r);
        float og = 1.0f - gamma;
        int start = __ldg(row_start + node);
        int d = __ldg(deg + node);
        float4 acc = make_float4(0.f, 0.f, 0.f, 0.f);

        for (int base = 0; base < d; base += GPN) {
            int cnt = min(GPN, d - base);
            ull p = 0;
            if (g < cnt) p = __ldg(csr + start + base + g);
            if (cnt == GPN) {
#pragma unroll
                for (int j = 0; j < GPN; j++) {
                    ull pj = __shfl_sync(gmask, p, j, GPN);
                    int s = (int)(unsigned)pj;
                    float n = __uint_as_float((unsigned)(pj >> 32));
                    uint2 hv2 = __ldg((const uint2*)(hh + (size_t)s * C) + g);
                    float2 fa = __half22float2(*(__half2*)&hv2.x);
                    float2 fb = __half22float2(*(__half2*)&hv2.y);
                    acc.x = fmaf(n, fa.x, acc.x);
                    acc.y = fmaf(n, fa.y, acc.y);
                    acc.z = fmaf(n, fb.x, acc.z);
                    acc.w = fmaf(n, fb.y, acc.w);
                }
            } else {
                for (int j = 0; j < cnt; j++) {
                    ull pj = __shfl_sync(gmask, p, j, GPN);
                    int s = (int)(unsigned)pj;
                    float n = __uint_as_float((unsigned)(pj >> 32));
                    uint2 hv2 = __ldg((const uint2*)(hh + (size_t)s * C) + g);
                    float2 fa = __half22float2(*(__half2*)&hv2.x);
                    float2 fb = __half22float2(*(__half2*)&hv2.y);
                    acc.x = fmaf(n, fa.x, acc.x);
                    acc.y = fmaf(n, fa.y, acc.y);
                    acc.z = fmaf(n, fb.x, acc.z);
                    acc.w = fmaf(n, fb.y, acc.w);
                }
            }
        }

        float4 hv = __ldg((const float4*)(h + (size_t)node * C) + g);
        float4 xv;
        xv.x = fmaf(gamma, acc.x, og * hv.x);
        xv.y = fmaf(gamma, acc.y, og * hv.y);
        xv.z = fmaf(gamma, acc.z, og * hv.z);
        xv.w = fmaf(gamma, acc.w, og * hv.w);
        ((float4*)(x + (size_t)node * C))[g] = xv;

        int c0 = g * 4;
        atomicAdd(&sstats[c0 + 0], xv.x);
        atomicAdd(&sstats[c0 + 1], xv.y);
        atomicAdd(&sstats[c0 + 2], xv.z);
        atomicAdd(&sstats[c0 + 3], xv.w);
        atomicAdd(&sstats[C + c0 + 0], xv.x * xv.x);
        atomicAdd(&sstats[C + c0 + 1], xv.y * xv.y);
        atomicAdd(&sstats[C + c0 + 2], xv.z * xv.z);
        atomicAdd(&sstats[C + c0 + 3], xv.w * xv.w);
    }
    __syncthreads();
    for (int i = tid; i < 2 * C; i += 256) atomicAdd(&stats[i], sstats[i]);
}

// ---------------- out: BN2 fold (inline) + relu + log_softmax ---------------
__global__ __launch_bounds__(256) void out_kernel(
    const float* __restrict__ x2, const int* __restrict__ bnodes,
    const float* __restrict__ stats, const float* __restrict__ bnscale,
    const float* __restrict__ bnbias, float* __restrict__ out, int r)
{
    __shared__ float sa[OO], sb[OO];
    if (threadIdx.x < OO) {
        int c = threadIdx.x;
        float mean = __ldg(stats + c) * (1.0f / NN);
        float var = __ldg(stats + OO + c) * (1.0f / NN) - mean * mean;
        float inv = rsqrtf(var + 1e-5f);
        float a = __ldg(bnscale + c) * inv;
        sa[c] = a;
        sb[c] = __ldg(bnbias + c) - mean * a;
    }
    __syncthreads();

    int idx = blockIdx.x * blockDim.x + threadIdx.x;
    int b = idx >> 5;
    int lane = idx & 31;
    if (b >= BB) return;
    int node = __ldg(bnodes + b);
    float v = x2[(size_t)node * OO + lane];
    v = fmaxf(0.f, fmaf(v, sa[lane], sb[lane]));
    float m = v;
#pragma unroll
    for (int o = 16; o; o >>= 1) m = fmaxf(m, __shfl_xor_sync(0xffffffffu, m, o));
    float e = expf(v - m);
    float ssum = e;
#pragma unroll
    for (int o = 16; o; o >>= 1) ssum += __shfl_xor_sync(0xffffffffu, ssum, o);
    out[(size_t)b * (RR * OO) + r * OO + lane] = v - m - logf(ssum);
}

// ---------------- launcher ----------------
static void build_csr_rel(int r, const int* edge_index, cudaStream_t s,
                          int* deg, int* rows, ull* csr,
                          float* dinv, int* cur, int* bs)
{
    const int* src = edge_index + (size_t)r * 2 * EE;
    const int* dst = src + EE;
    cudaMemsetAsync(deg, 0, NN * sizeof(int), s);
    degree_kernel<<<(EE / 4 + 255) / 256, 256, 0, s>>>(dst, deg);
    scan_block<<<SCAN_BLKS, 1024, 0, s>>>(deg, rows, bs, dinv);
    scan_sums<<<1, 32, 0, s>>>(bs);
    scan_add<<<SCAN_BLKS, 1024, 0, s>>>(rows, bs, cur);
    fill_csr<<<(EE + 255) / 256, 256, 0, s>>>(src, dst, dinv, cur, csr);
}

extern "C" void kernel_launch(void* const* d_in, const int* in_sizes, int n_in,
                              void* d_out, int out_size)
{
    const float* features    = (const float*)d_in[0];
    const int*   edge_index  = (const int*)d_in[1];
    const int*   batch_nodes = (const int*)d_in[2];
    const float* W1 = (const float*)d_in[3];
    const float* b1 = (const float*)d_in[4];
    const float* W2 = (const float*)d_in[5];
    const float* b2 = (const float*)d_in[6];
    const float* gamma1 = (const float*)d_in[7];
    const float* gamma2 = (const float*)d_in[8];
    const float* bn1s = (const float*)d_in[9];
    const float* bn1b = (const float*)d_in[10];
    const float* bn2s = (const float*)d_in[11];
    const float* bn2b = (const float*)d_in[12];
    float* out = (float*)d_out;

    static cudaStream_t sB = nullptr, sC = nullptr;
    static cudaEvent_t e_fork, evC[RR], evH1, evE1;
    if (sB == nullptr) {
        cudaStreamCreateWithFlags(&sB, cudaStreamNonBlocking);
        cudaStreamCreateWithFlags(&sC, cudaStreamNonBlocking);
        cudaEventCreateWithFlags(&e_fork, cudaEventDisableTiming);
        cudaEventCreateWithFlags(&evH1, cudaEventDisableTiming);
        cudaEventCreateWithFlags(&evE1, cudaEventDisableTiming);
        for (int i = 0; i < RR; i++)
            cudaEventCreateWithFlags(&evC[i], cudaEventDisableTiming);
    }

    void *p_deg, *p_rows, *p_csr, *p_dinv, *p_cur, *p_bs,
         *p_feath, *p_w1h, *p_h1, *p_h1h, *p_x1, *p_h2, *p_h2h, *p_x2,
         *p_s1, *p_s2;
    cudaGetSymbolAddress(&p_deg, g_deg);
    cudaGetSymbolAddress(&p_rows, g_rows);
    cudaGetSymbolAddress(&p_csr, g_csr);
    cudaGetSymbolAddress(&p_dinv, g_dinv);
    cudaGetSymbolAddress(&p_cur, g_cursor);
    cudaGetSymbolAddress(&p_bs, g_bsums);
    cudaGetSymbolAddress(&p_feath, g_feat_h);
    cudaGetSymbolAddress(&p_w1h, g_W1h);
    cudaGetSymbolAddress(&p_h1, g_h1);
    cudaGetSymbolAddress(&p_h1h, g_h1h);
    cudaGetSymbolAddress(&p_x1, g_x1);
    cudaGetSymbolAddress(&p_h2, g_h2);
    cudaGetSymbolAddress(&p_h2h, g_h2h);
    cudaGetSymbolAddress(&p_x2, g_x2);
    cudaGetSymbolAddress(&p_s1, g_stats1);
    cudaGetSymbolAddress(&p_s2, g_stats2);

    auto DEG  = [&](int r){ return (int*)p_deg + (size_t)r * NN; };
    auto ROWS = [&](int r){ return (int*)p_rows + (size_t)r * NN; };
    auto CSR  = [&](int r){ return (ull*)p_csr + (size_t)r * EE; };
    auto H1   = [&](int r){ return (float*)p_h1 + (size_t)r * NN * HH; };
    auto H1H  = [&](int r){ return (__half*)p_h1h + (size_t)r * NN * HH; };
    auto X1   = [&](int r){ return (float*)p_x1 + (size_t)r * NN * HH; };
    auto H2   = [&](int r){ return (float*)p_h2 + (size_t)r * NN * OO; };
    auto H2H  = [&](int r){ return (__half*)p_h2h + (size_t)r * NN * OO; };
    auto X2   = [&](int r){ return (float*)p_x2 + (size_t)r * NN * OO; };
    auto S1   = [&](int r){ return (float*)p_s1 + (size_t)r * 2 * HH; };
    auto S2   = [&](int r){ return (float*)p_s2 + (size_t)r * 2 * OO; };

    const int GEMM_GRID = (NN + 255) / 256;
    const int MMA_GRID  = NPAD / 64;

    // zero all stats up-front (off the chains)
    cudaMemsetAsync(p_s1, 0, RR * 2 * HH * sizeof(float));
    cudaMemsetAsync(p_s2, 0, RR * 2 * OO * sizeof(float));

    // fp16 conversions
    cvt_feat<<<(NPAD * FF / 4 + 255) / 256, 256>>>(features);
    cvt_w<<<(RR * FF * HH / 4 + 255) / 256, 256>>>(W1);

    // fork side streams
    cudaEventRecord(e_fork, 0);
    cudaStreamWaitEvent(sB, e_fork, 0);
    cudaStreamWaitEvent(sC, e_fork, 0);

    // all three builds up-front on sB (triple-buffered, serialize on sB)
    for (int r = 0; r < RR; r++) {
        build_csr_rel(r, edge_index, sB, DEG(r), ROWS(r), CSR(r),
                      (float*)p_dinv, (int*)p_cur, (int*)p_bs);
        cudaEventRecord(evC[r], sB);
    }

    // all three gemm1s up-front on main
    for (int r = 0; r < RR; r++) {
        gemm1_mma<<<MMA_GRID, 128>>>(
            (const __half*)p_feath, (const __half*)p_w1h + (size_t)r * FF * HH,
            b1 + r * HH, H1(r), H1H(r), NN);
        if (r == 1) cudaEventRecord(evH1, 0);
    }

    // chain: gather1 -> gemm2(BN inline) -> gather2 -> out(BN inline)
    auto chain = [&](int r, cudaStream_t s) {
        gather_combine<HH><<<(NN + 15) / 16, 256, 0, s>>>(
            H1(r), H1H(r), CSR(r), ROWS(r), DEG(r), gamma1, r, X1(r), S1(r));
        gemm_tiled<HH, OO, true><<<GEMM_GRID, 256, 0, s>>>(
            X1(r), W2 + (size_t)r * HH * OO, b2 + r * OO,
            S1(r), bn1s + r * HH, bn1b + r * HH, H2(r), H2H(r), NN);
        gather_combine<OO><<<(NN + 31) / 32, 256, 0, s>>>(
            H2(r), H2H(r), CSR(r), ROWS(r), DEG(r), gamma2, r, X2(r), S2(r));
        out_kernel<<<(BB * 32 + 255) / 256, 256, 0, s>>>(
            X2(r), batch_nodes, S2(r), bn2s + r * OO, bn2b + r * OO, out, r);
    };

    // relation 1 chain on sC (deps: gemm1(1) via evH1, build1 via evC[1])
    cudaStreamWaitEvent(sC, evH1, 0);
    cudaStreamWaitEvent(sC, evC[1], 0);
    chain(1, sC);
    cudaEventRecord(evE1, sC);

    // relations 0 and 2 on main
    cudaStreamWaitEvent(0, evC[0], 0);
    chain(0, 0);
    cudaStreamWaitEvent(0, evC[2], 0);
    chain(2, 0);

    // join sC back into main before capture ends
    cudaStreamWaitEvent(0, evE1, 0);
}

// round 16
// speedup vs baseline: 1.3505x; 1.0570x over previous
#include <cuda_runtime.h>
#include <cuda_fp16.h>

#define NN 100000
#define EE 1600000
#define RR 3
#define FF 128
#define HH 64
#define OO 32
#define BB 50000
#define SCAN_BLKS ((NN + 1023) / 1024)
#define NPAD 100096            // 1564 * 64, padded row count for mma tiles

typedef unsigned long long ull;

// ---------------- scratch (triple-buffered per relation) ----------------
__device__ int    g_deg[RR][NN];
__device__ int    g_rows[RR][NN];
__device__ ull    g_csr[RR][EE];     // packed (src:int low32, norm:float high32)
__device__ float  g_dinv[NN];
__device__ int    g_cursor[NN];
__device__ int    g_bsums[SCAN_BLKS];
__device__ __half g_feat_h[(size_t)NPAD * FF];
__device__ __half g_W1h[RR * FF * HH];
__device__ __half g_W2h[RR * HH * OO];
__device__ __half g_h1h[RR][NN * HH];   // fp16-only feature path
__device__ __half g_x1h[RR][NN * HH];
__device__ __half g_h2h[RR][NN * OO];
__device__ float  g_x2[RR][NN * OO];    // final stage stays fp32
__device__ float  g_stats1[RR][2 * HH];
__device__ float  g_stats2[RR][2 * OO];

// ---------------- mma helpers ----------------
__device__ __forceinline__ void ldsm4(unsigned& d0, unsigned& d1,
                                      unsigned& d2, unsigned& d3, unsigned addr)
{
    asm volatile("ldmatrix.sync.aligned.m8n8.x4.shared.b16 {%0,%1,%2,%3}, [%4];"
                 : "=r"(d0), "=r"(d1), "=r"(d2), "=r"(d3) : "r"(addr));
}
__device__ __forceinline__ void ldsm4t(unsigned& d0, unsigned& d1,
                                       unsigned& d2, unsigned& d3, unsigned addr)
{
    asm volatile("ldmatrix.sync.aligned.m8n8.x4.trans.shared.b16 {%0,%1,%2,%3}, [%4];"
                 : "=r"(d0), "=r"(d1), "=r"(d2), "=r"(d3) : "r"(addr));
}
__device__ __forceinline__ void mma16816(float* c,
    unsigned a0, unsigned a1, unsigned a2, unsigned a3,
    unsigned b0, unsigned b1)
{
    asm volatile(
        "mma.sync.aligned.m16n8k16.row.col.f32.f16.f16.f32 "
        "{%0,%1,%2,%3}, {%4,%5,%6,%7}, {%8,%9}, {%0,%1,%2,%3};"
        : "+f"(c[0]), "+f"(c[1]), "+f"(c[2]), "+f"(c[3])
        : "r"(a0), "r"(a1), "r"(a2), "r"(a3), "r"(b0), "r"(b1));
}

// ---------------- fp16 conversion kernels ----------------
__global__ __launch_bounds__(256) void cvt_feat(const float* __restrict__ f)
{
    int i = blockIdx.x * blockDim.x + threadIdx.x;
    if (i >= NPAD * FF / 4) return;
    float4 v = make_float4(0.f, 0.f, 0.f, 0.f);
    if (i < NN * FF / 4) v = __ldg((const float4*)f + i);
    __half2 h0 = __floats2half2_rn(v.x, v.y);
    __half2 h1 = __floats2half2_rn(v.z, v.w);
    uint2 o;
    o.x = *(unsigned*)&h0;
    o.y = *(unsigned*)&h1;
    *(uint2*)(g_feat_h + (size_t)i * 4) = o;
}

__global__ __launch_bounds__(256) void cvt_w(const float* __restrict__ W1,
                                             const float* __restrict__ W2)
{
    int i = blockIdx.x * blockDim.x + threadIdx.x;
    int n1 = RR * FF * HH / 4;
    int n2 = RR * HH * OO / 4;
    if (i < n1) {
        float4 v = __ldg((const float4*)W1 + i);
        __half2 h0 = __floats2half2_rn(v.x, v.y);
        __half2 h1 = __floats2half2_rn(v.z, v.w);
        uint2 o;
        o.x = *(unsigned*)&h0;
        o.y = *(unsigned*)&h1;
        *(uint2*)(g_W1h + (size_t)i * 4) = o;
    } else if (i < n1 + n2) {
        int j = i - n1;
        float4 v = __ldg((const float4*)W2 + j);
        __half2 h0 = __floats2half2_rn(v.x, v.y);
        __half2 h1 = __floats2half2_rn(v.z, v.w);
        uint2 o;
        o.x = *(unsigned*)&h0;
        o.y = *(unsigned*)&h1;
        *(uint2*)(g_W2h + (size_t)j * 4) = o;
    }
}

// ---------------- conv1 GEMM via HMMA: h1h = feat @ W1 + b (fp16 out) ------
#define XS 136
#define WS 72
__global__ __launch_bounds__(128) void gemm1_mma(
    const __half* __restrict__ Xh, const __half* __restrict__ Wh,
    const float* __restrict__ bg, __half* __restrict__ Yh, int nrows)
{
    __shared__ __half sX[64 * XS];
    __shared__ __half sW[FF * WS];
    int tid = threadIdx.x;
    int wid = tid >> 5, lane = tid & 31;
    int row0 = blockIdx.x * 64;

    for (int i = tid; i < FF * 8; i += 128) {
        int rk = i >> 3, c = i & 7;
        uint4 v = __ldg((const uint4*)(Wh + (size_t)rk * HH) + c);
        *(uint4*)(sW + rk * WS + c * 8) = v;
    }
    for (int i = tid; i < 64 * 16; i += 128) {
        int rr = i >> 4, c = i & 15;
        uint4 v = __ldg((const uint4*)(Xh + (size_t)(row0 + rr) * FF) + c);
        *(uint4*)(sX + rr * XS + c * 8) = v;
    }
    __syncthreads();

    float acc[8][4];
#pragma unroll
    for (int j = 0; j < 8; j++)
#pragma unroll
        for (int q = 0; q < 4; q++) acc[j][q] = 0.f;

    int m = lane >> 3, r7 = lane & 7;
#pragma unroll
    for (int ks = 0; ks < 8; ks++) {
        unsigned a0, a1, a2, a3;
        unsigned aaddr = (unsigned)__cvta_generic_to_shared(
            sX + (16 * wid + (m & 1) * 8 + r7) * XS + ks * 16 + (m >> 1) * 8);
        ldsm4(a0, a1, a2, a3, aaddr);
#pragma unroll
        for (int jp = 0; jp < 4; jp++) {
            unsigned b0, b1, b2, b3;
            unsigned baddr = (unsigned)__cvta_generic_to_shared(
                sW + (ks * 16 + (m & 1) * 8 + r7) * WS + jp * 16 + (m >> 1) * 8);
            ldsm4t(b0, b1, b2, b3, baddr);
            mma16816(acc[2 * jp],     a0, a1, a2, a3, b0, b1);
            mma16816(acc[2 * jp + 1], a0, a1, a2, a3, b2, b3);
        }
    }

    int rbase = row0 + 16 * wid + (lane >> 2);
    int cb = (lane & 3) * 2;
#pragma unroll
    for (int j = 0; j < 8; j++) {
        int col = j * 8 + cb;
        float bx = __ldg(bg + col), by = __ldg(bg + col + 1);
        if (rbase < nrows) {
            __half2 h = __floats2half2_rn(acc[j][0] + bx, acc[j][1] + by);
            *(unsigned*)(Yh + (size_t)rbase * HH + col) = *(unsigned*)&h;
        }
        if (rbase + 8 < nrows) {
            __half2 h = __floats2half2_rn(acc[j][2] + bx, acc[j][3] + by);
            *(unsigned*)(Yh + (size_t)(rbase + 8) * HH + col) = *(unsigned*)&h;
        }
    }
}

// ---------------- conv2 GEMM via HMMA with inline BN1 fold + relu ----------
#define XS2 72
#define WS2 40
__global__ __launch_bounds__(128) void gemm2_mma(
    const __half* __restrict__ Xh, const __half* __restrict__ W2h,
    const float* __restrict__ bg,
    const float* __restrict__ stats, const float* __restrict__ bnscale,
    const float* __restrict__ bnbias,
    __half* __restrict__ Yh, int nrows)
{
    __shared__ __half sX[64 * XS2];
    __shared__ __half sW[HH * WS2];
    __shared__ float sA[HH], sB[HH];
    int tid = threadIdx.x;
    int wid = tid >> 5, lane = tid & 31;
    int row0 = blockIdx.x * 64;

    if (tid < HH) {
        float mean = __ldg(stats + tid) * (1.0f / NN);
        float var = __ldg(stats + HH + tid) * (1.0f / NN) - mean * mean;
        float inv = rsqrtf(var + 1e-5f);
        float a = __ldg(bnscale + tid) * inv;
        sA[tid] = a;
        sB[tid] = __ldg(bnbias + tid) - mean * a;
    }
    __syncthreads();

    // stage W2 [64 x 32] fp16
    for (int i = tid; i < HH * 4; i += 128) {
        int rk = i >> 2, c = i & 3;
        uint4 v = __ldg((const uint4*)(W2h + (size_t)rk * OO) + c);
        *(uint4*)(sW + rk * WS2 + c * 8) = v;
    }
    // stage X [64 x 64] fp16 with fp32 BN+relu applied on load
    for (int i = tid; i < 64 * 8; i += 128) {
        int rr = i >> 3, c = i & 7;
        int row = row0 + rr;
        uint4 v = make_uint4(0, 0, 0, 0);
        if (row < nrows) v = __ldg((const uint4*)(Xh + (size_t)row * HH) + c);
        int k0 = c * 8;
        unsigned vp[4] = {v.x, v.y, v.z, v.w};
#pragma unroll
        for (int p = 0; p < 4; p++) {
            __half2 h = *(__half2*)&vp[p];
            float2 f = __half22float2(h);
            f.x = fmaxf(0.f, fmaf(f.x, sA[k0 + 2 * p],     sB[k0 + 2 * p]));
            f.y = fmaxf(0.f, fmaf(f.y, sA[k0 + 2 * p + 1], sB[k0 + 2 * p + 1]));
            __half2 o = __floats2half2_rn(f.x, f.y);
            vp[p] = *(unsigned*)&o;
        }
        uint4 ov;
        ov.x = vp[0]; ov.y = vp[1]; ov.z = vp[2]; ov.w = vp[3];
        *(uint4*)(sX + rr * XS2 + c * 8) = ov;
    }
    __syncthreads();

    float acc[4][4];
#pragma unroll
    for (int j = 0; j < 4; j++)
#pragma unroll
        for (int q = 0; q < 4; q++) acc[j][q] = 0.f;

    int m = lane >> 3, r7 = lane & 7;
#pragma unroll
    for (int ks = 0; ks < 4; ks++) {
        unsigned a0, a1, a2, a3;
        unsigned aaddr = (unsigned)__cvta_generic_to_shared(
            sX + (16 * wid + (m & 1) * 8 + r7) * XS2 + ks * 16 + (m >> 1) * 8);
        ldsm4(a0, a1, a2, a3, aaddr);
#pragma unroll
        for (int jp = 0; jp < 2; jp++) {
            unsigned b0, b1, b2, b3;
            unsigned baddr = (unsigned)__cvta_generic_to_shared(
                sW + (ks * 16 + (m & 1) * 8 + r7) * WS2 + jp * 16 + (m >> 1) * 8);
            ldsm4t(b0, b1, b2, b3, baddr);
            mma16816(acc[2 * jp],     a0, a1, a2, a3, b0, b1);
            mma16816(acc[2 * jp + 1], a0, a1, a2, a3, b2, b3);
        }
    }

    int rbase = row0 + 16 * wid + (lane >> 2);
    int cb = (lane & 3) * 2;
#pragma unroll
    for (int j = 0; j < 4; j++) {
        int col = j * 8 + cb;
        float bx = __ldg(bg + col), by = __ldg(bg + col + 1);
        if (rbase < nrows) {
            __half2 h = __floats2half2_rn(acc[j][0] + bx, acc[j][1] + by);
            *(unsigned*)(Yh + (size_t)rbase * OO + col) = *(unsigned*)&h;
        }
        if (rbase + 8 < nrows) {
            __half2 h = __floats2half2_rn(acc[j][2] + bx, acc[j][3] + by);
            *(unsigned*)(Yh + (size_t)(rbase + 8) * OO + col) = *(unsigned*)&h;
        }
    }
}

// ---------------- CSR build kernels ----------------
__global__ __launch_bounds__(256) void degree_kernel(
    const int* __restrict__ dst, int* __restrict__ deg)
{
    int e4 = blockIdx.x * blockDim.x + threadIdx.x;
    if (e4 < EE / 4) {
        int4 d = __ldg((const int4*)dst + e4);
        atomicAdd(deg + d.x, 1);
        atomicAdd(deg + d.y, 1);
        atomicAdd(deg + d.z, 1);
        atomicAdd(deg + d.w, 1);
    }
}

__global__ __launch_bounds__(1024) void scan_block(
    const int* __restrict__ deg, int* __restrict__ out,
    int* __restrict__ bsums, float* __restrict__ dinv)
{
    __shared__ int sh[1024];
    int i = blockIdx.x * 1024 + threadIdx.x;
    int v = (i < NN) ? deg[i] : 0;
    if (i < NN) dinv[i] = rsqrtf(fmaxf((float)v, 1.0f));
    sh[threadIdx.x] = v;
    __syncthreads();
#pragma unroll
    for (int off = 1; off < 1024; off <<= 1) {
        int t = (threadIdx.x >= off) ? sh[threadIdx.x - off] : 0;
        __syncthreads();
        sh[threadIdx.x] += t;
        __syncthreads();
    }
    if (i < NN) out[i] = sh[threadIdx.x] - v;
    if (threadIdx.x == 1023) bsums[blockIdx.x] = sh[1023];
}

__global__ void scan_sums(int* __restrict__ bsums)
{
    if (threadIdx.x == 0) {
        int acc = 0;
        for (int i = 0; i < SCAN_BLKS; i++) {
            int t = bsums[i]; bsums[i] = acc; acc += t;
        }
    }
}

__global__ __launch_bounds__(1024) void scan_add(
    int* __restrict__ out, const int* __restrict__ bsums, int* __restrict__ cursor)
{
    int i = blockIdx.x * 1024 + threadIdx.x;
    if (i < NN) {
        int v = out[i] + bsums[blockIdx.x];
        out[i] = v;
        cursor[i] = v;
    }
}

__global__ __launch_bounds__(256) void fill_csr(
    const int* __restrict__ src, const int* __restrict__ dst,
    const float* __restrict__ dinv, int* __restrict__ cursor,
    ull* __restrict__ csr)
{
    int e = blockIdx.x * blockDim.x + threadIdx.x;
    if (e >= EE) return;
    int s = __ldg(src + e);
    int d = __ldg(dst + e);
    int pos = atomicAdd(cursor + d, 1);
    float norm = __ldg(dinv + s) * __ldg(dinv + d);
    csr[pos] = (ull)(unsigned)s | ((ull)__float_as_uint(norm) << 32);
}

// ---------------- fused gather(fp16) + combine + BN stats ----------------
// HOUT: write fp16 output; else fp32.
template <int C, bool HOUT>
__global__ __launch_bounds__(256) void gather_combine(
    const __half* __restrict__ hh, const ull* __restrict__ csr,
    const int* __restrict__ row_start, const int* __restrict__ deg,
    const float* __restrict__ gammaArr, int r,
    void* __restrict__ xout, float* __restrict__ stats)
{
    constexpr int GPN = C / 4;
    constexpr int NPB = 256 / GPN;
    __shared__ float sstats[2 * C];
    int tid = threadIdx.x;
    for (int i = tid; i < 2 * C; i += 256) sstats[i] = 0.f;
    __syncthreads();

    int g = tid & (GPN - 1);
    int node = blockIdx.x * NPB + tid / GPN;
    unsigned gmask = ((1u << GPN) - 1u) << ((tid & 31) & ~(GPN - 1));

    if (node < NN) {
        float gamma = __ldg(gammaArr + r);
        float og = 1.0f - gamma;
        int start = __ldg(row_start + node);
        int d = __ldg(deg + node);
        float4 acc = make_float4(0.f, 0.f, 0.f, 0.f);

        for (int base = 0; base < d; base += GPN) {
            int cnt = min(GPN, d - base);
            ull p = 0;
            if (g < cnt) p = __ldg(csr + start + base + g);
            if (cnt == GPN) {
#pragma unroll
                for (int j = 0; j < GPN; j++) {
                    ull pj = __shfl_sync(gmask, p, j, GPN);
                    int s = (int)(unsigned)pj;
                    float n = __uint_as_float((unsigned)(pj >> 32));
                    uint2 hv2 = __ldg((const uint2*)(hh + (size_t)s * C) + g);
                    float2 fa = __half22float2(*(__half2*)&hv2.x);
                    float2 fb = __half22float2(*(__half2*)&hv2.y);
                    acc.x = fmaf(n, fa.x, acc.x);
                    acc.y = fmaf(n, fa.y, acc.y);
                    acc.z = fmaf(n, fb.x, acc.z);
                    acc.w = fmaf(n, fb.y, acc.w);
                }
            } else {
                for (int j = 0; j < cnt; j++) {
                    ull pj = __shfl_sync(gmask, p, j, GPN);
                    int s = (int)(unsigned)pj;
                    float n = __uint_as_float((unsigned)(pj >> 32));
                    uint2 hv2 = __ldg((const uint2*)(hh + (size_t)s * C) + g);
                    float2 fa = __half22float2(*(__half2*)&hv2.x);
                    float2 fb = __half22float2(*(__half2*)&hv2.y);
                    acc.x = fmaf(n, fa.x, acc.x);
                    acc.y = fmaf(n, fa.y, acc.y);
                    acc.z = fmaf(n, fb.x, acc.z);
                    acc.w = fmaf(n, fb.y, acc.w);
                }
            }
        }

        // self term from fp16
        uint2 sv = __ldg((const uint2*)(hh + (size_t)node * C) + g);
        float2 sa = __half22float2(*(__half2*)&sv.x);
        float2 sb = __half22float2(*(__half2*)&sv.y);
        float4 xv;
        xv.x = fmaf(gamma, acc.x, og * sa.x);
        xv.y = fmaf(gamma, acc.y, og * sa.y);
        xv.z = fmaf(gamma, acc.z, og * sb.x);
        xv.w = fmaf(gamma, acc.w, og * sb.y);

        if (HOUT) {
            __half2 o0 = __floats2half2_rn(xv.x, xv.y);
            __half2 o1 = __floats2half2_rn(xv.z, xv.w);
            uint2 o;
            o.x = *(unsigned*)&o0;
            o.y = *(unsigned*)&o1;
            ((uint2*)((__half*)xout + (size_t)node * C))[g] = o;
        } else {
            ((float4*)((float*)xout + (size_t)node * C))[g] = xv;
        }

        int c0 = g * 4;
        atomicAdd(&sstats[c0 + 0], xv.x);
        atomicAdd(&sstats[c0 + 1], xv.y);
        atomicAdd(&sstats[c0 + 2], xv.z);
        atomicAdd(&sstats[c0 + 3], xv.w);
        atomicAdd(&sstats[C + c0 + 0], xv.x * xv.x);
        atomicAdd(&sstats[C + c0 + 1], xv.y * xv.y);
        atomicAdd(&sstats[C + c0 + 2], xv.z * xv.z);
        atomicAdd(&sstats[C + c0 + 3], xv.w * xv.w);
    }
    __syncthreads();
    for (int i = tid; i < 2 * C; i += 256) atomicAdd(&stats[i], sstats[i]);
}

// ---------------- out: BN2 fold (inline) + relu + log_softmax ---------------
__global__ __launch_bounds__(256) void out_kernel(
    const float* __restrict__ x2, const int* __restrict__ bnodes,
    const float* __restrict__ stats, const float* __restrict__ bnscale,
    const float* __restrict__ bnbias, float* __restrict__ out, int r)
{
    __shared__ float sa[OO], sb[OO];
    if (threadIdx.x < OO) {
        int c = threadIdx.x;
        float mean = __ldg(stats + c) * (1.0f / NN);
        float var = __ldg(stats + OO + c) * (1.0f / NN) - mean * mean;
        float inv = rsqrtf(var + 1e-5f);
        float a = __ldg(bnscale + c) * inv;
        sa[c] = a;
        sb[c] = __ldg(bnbias + c) - mean * a;
    }
    __syncthreads();

    int idx = blockIdx.x * blockDim.x + threadIdx.x;
    int b = idx >> 5;
    int lane = idx & 31;
    if (b >= BB) return;
    int node = __ldg(bnodes + b);
    float v = x2[(size_t)node * OO + lane];
    v = fmaxf(0.f, fmaf(v, sa[lane], sb[lane]));
    float m = v;
#pragma unroll
    for (int o = 16; o; o >>= 1) m = fmaxf(m, __shfl_xor_sync(0xffffffffu, m, o));
    float e = expf(v - m);
    float ssum = e;
#pragma unroll
    for (int o = 16; o; o >>= 1) ssum += __shfl_xor_sync(0xffffffffu, ssum, o);
    out[(size_t)b * (RR * OO) + r * OO + lane] = v - m - logf(ssum);
}

// ---------------- launcher ----------------
static void build_csr_rel(int r, const int* edge_index, cudaStream_t s,
                          int* deg, int* rows, ull* csr,
                          float* dinv, int* cur, int* bs)
{
    const int* src = edge_index + (size_t)r * 2 * EE;
    const int* dst = src + EE;
    cudaMemsetAsync(deg, 0, NN * sizeof(int), s);
    degree_kernel<<<(EE / 4 + 255) / 256, 256, 0, s>>>(dst, deg);
    scan_block<<<SCAN_BLKS, 1024, 0, s>>>(deg, rows, bs, dinv);
    scan_sums<<<1, 32, 0, s>>>(bs);
    scan_add<<<SCAN_BLKS, 1024, 0, s>>>(rows, bs, cur);
    fill_csr<<<(EE + 255) / 256, 256, 0, s>>>(src, dst, dinv, cur, csr);
}

extern "C" void kernel_launch(void* const* d_in, const int* in_sizes, int n_in,
                              void* d_out, int out_size)
{
    const float* features    = (const float*)d_in[0];
    const int*   edge_index  = (const int*)d_in[1];
    const int*   batch_nodes = (const int*)d_in[2];
    const float* W1 = (const float*)d_in[3];
    const float* b1 = (const float*)d_in[4];
    const float* W2 = (const float*)d_in[5];
    const float* b2 = (const float*)d_in[6];
    const float* gamma1 = (const float*)d_in[7];
    const float* gamma2 = (const float*)d_in[8];
    const float* bn1s = (const float*)d_in[9];
    const float* bn1b = (const float*)d_in[10];
    const float* bn2s = (const float*)d_in[11];
    const float* bn2b = (const float*)d_in[12];
    float* out = (float*)d_out;

    static cudaStream_t sB = nullptr, sC = nullptr;
    static cudaEvent_t e_fork, evC[RR], evH1, evE1;
    if (sB == nullptr) {
        cudaStreamCreateWithFlags(&sB, cudaStreamNonBlocking);
        cudaStreamCreateWithFlags(&sC, cudaStreamNonBlocking);
        cudaEventCreateWithFlags(&e_fork, cudaEventDisableTiming);
        cudaEventCreateWithFlags(&evH1, cudaEventDisableTiming);
        cudaEventCreateWithFlags(&evE1, cudaEventDisableTiming);
        for (int i = 0; i < RR; i++)
            cudaEventCreateWithFlags(&evC[i], cudaEventDisableTiming);
    }

    void *p_deg, *p_rows, *p_csr, *p_dinv, *p_cur, *p_bs,
         *p_feath, *p_w1h, *p_w2h, *p_h1h, *p_x1h, *p_h2h, *p_x2,
         *p_s1, *p_s2;
    cudaGetSymbolAddress(&p_deg, g_deg);
    cudaGetSymbolAddress(&p_rows, g_rows);
    cudaGetSymbolAddress(&p_csr, g_csr);
    cudaGetSymbolAddress(&p_dinv, g_dinv);
    cudaGetSymbolAddress(&p_cur, g_cursor);
    cudaGetSymbolAddress(&p_bs, g_bsums);
    cudaGetSymbolAddress(&p_feath, g_feat_h);
    cudaGetSymbolAddress(&p_w1h, g_W1h);
    cudaGetSymbolAddress(&p_w2h, g_W2h);
    cudaGetSymbolAddress(&p_h1h, g_h1h);
    cudaGetSymbolAddress(&p_x1h, g_x1h);
    cudaGetSymbolAddress(&p_h2h, g_h2h);
    cudaGetSymbolAddress(&p_x2, g_x2);
    cudaGetSymbolAddress(&p_s1, g_stats1);
    cudaGetSymbolAddress(&p_s2, g_stats2);

    auto DEG  = [&](int r){ return (int*)p_deg + (size_t)r * NN; };
    auto ROWS = [&](int r){ return (int*)p_rows + (size_t)r * NN; };
    auto CSR  = [&](int r){ return (ull*)p_csr + (size_t)r * EE; };
    auto H1H  = [&](int r){ return (__half*)p_h1h + (size_t)r * NN * HH; };
    auto X1H  = [&](int r){ return (__half*)p_x1h + (size_t)r * NN * HH; };
    auto H2H  = [&](int r){ return (__half*)p_h2h + (size_t)r * NN * OO; };
    auto X2   = [&](int r){ return (float*)p_x2 + (size_t)r * NN * OO; };
    auto S1   = [&](int r){ return (float*)p_s1 + (size_t)r * 2 * HH; };
    auto S2   = [&](int r){ return (float*)p_s2 + (size_t)r * 2 * OO; };

    const int MMA_GRID  = NPAD / 64;
    const int MMA2_GRID = (NN + 63) / 64;

    // zero all stats up-front (off the chains)
    cudaMemsetAsync(p_s1, 0, RR * 2 * HH * sizeof(float));
    cudaMemsetAsync(p_s2, 0, RR * 2 * OO * sizeof(float));

    // fp16 conversions
    cvt_feat<<<(NPAD * FF / 4 + 255) / 256, 256>>>(features);
    cvt_w<<<((RR * FF * HH + RR * HH * OO) / 4 + 255) / 256, 256>>>(W1, W2);

    // fork side streams
    cudaEventRecord(e_fork, 0);
    cudaStreamWaitEvent(sB, e_fork, 0);
    cudaStreamWaitEvent(sC, e_fork, 0);

    // all three builds up-front on sB (triple-buffered, serialize on sB)
    for (int r = 0; r < RR; r++) {
        build_csr_rel(r, edge_index, sB, DEG(r), ROWS(r), CSR(r),
                      (float*)p_dinv, (int*)p_cur, (int*)p_bs);
        cudaEventRecord(evC[r], sB);
    }

    // all three gemm1s up-front on main
    for (int r = 0; r < RR; r++) {
        gemm1_mma<<<MMA_GRID, 128>>>(
            (const __half*)p_feath, (const __half*)p_w1h + (size_t)r * FF * HH,
            b1 + r * HH, H1H(r), NN);
        if (r == 1) cudaEventRecord(evH1, 0);
    }

    // chain: gather1(fp16 out) -> gemm2 HMMA(BN inline) -> gather2 -> out
    auto chain = [&](int r, cudaStream_t s) {
        gather_combine<HH, true><<<(NN + 15) / 16, 256, 0, s>>>(
            H1H(r), CSR(r), ROWS(r), DEG(r), gamma1, r, X1H(r), S1(r));
        gemm2_mma<<<MMA2_GRID, 128, 0, s>>>(
            X1H(r), (const __half*)p_w2h + (size_t)r * HH * OO, b2 + r * OO,
            S1(r), bn1s + r * HH, bn1b + r * HH, H2H(r), NN);
        gather_combine<OO, false><<<(NN + 31) / 32, 256, 0, s>>>(
            H2H(r), CSR(r), ROWS(r), DEG(r), gamma2, r, X2(r), S2(r));
        out_kernel<<<(BB * 32 + 255) / 256, 256, 0, s>>>(
            X2(r), batch_nodes, S2(r), bn2s + r * OO, bn2b + r * OO, out, r);
    };

    // relation 1 chain on sC (deps: gemm1(1) via evH1, build1 via evC[1])
    cudaStreamWaitEvent(sC, evH1, 0);
    cudaStreamWaitEvent(sC, evC[1], 0);
    chain(1, sC);
    cudaEventRecord(evE1, sC);

    // relations 0 and 2 on main
    cudaStreamWaitEvent(0, evC[0], 0);
    chain(0, 0);
    cudaStreamWaitEvent(0, evC[2], 0);
    chain(2, 0);

    // join sC back into main before capture ends
    cudaStreamWaitEvent(0, evE1, 0);
}